// round 1
// baseline (speedup 1.0000x reference)
#include <cuda_runtime.h>
#include <math.h>

// Problem constants
#define RTOK 2048          // total rows = 2*1024 tokens
#define DIM  1024
#define NH   16
#define HDIM 64
#define MLPD 4096
#define NBH  32            // 2 batches * 16 heads
#define SEQ  1024

// ---------------- scratch (device globals; no runtime allocation) ----------
__device__ float g_x   [RTOK * DIM];          //  8 MB  running residual
__device__ float g_xn  [RTOK * DIM];          //  8 MB  layernorm output
__device__ float g_qkv [RTOK * 3 * DIM];      // 25 MB
__device__ float g_s   [(size_t)NBH * SEQ * SEQ]; // 134 MB attention scores
__device__ float g_attn[RTOK * DIM];          //  8 MB
__device__ float g_h   [RTOK * MLPD];         // 33 MB

// ---------------- reductions ----------------
__device__ __forceinline__ float warp_sum(float v) {
#pragma unroll
    for (int o = 16; o; o >>= 1) v += __shfl_xor_sync(0xffffffffu, v, o);
    return v;
}
__device__ __forceinline__ float warp_max(float v) {
#pragma unroll
    for (int o = 16; o; o >>= 1) v = fmaxf(v, __shfl_xor_sync(0xffffffffu, v, o));
    return v;
}

// ---------------- layernorm: one block per row of 1024 ----------------
__global__ __launch_bounds__(256) void ln_kernel(
    const float* __restrict__ X, const float* __restrict__ G,
    const float* __restrict__ B, float* __restrict__ Y)
{
    __shared__ float red[8];
    int row = blockIdx.x;
    int tid = threadIdx.x;
    int lane = tid & 31, wid = tid >> 5;

    float4 v = reinterpret_cast<const float4*>(X + (size_t)row * DIM)[tid];

    // mean
    float s = v.x + v.y + v.z + v.w;
    s = warp_sum(s);
    if (lane == 0) red[wid] = s;
    __syncthreads();
    if (wid == 0) {
        float t = (lane < 8) ? red[lane] : 0.f;
        t = warp_sum(t);
        if (lane == 0) red[0] = t;
    }
    __syncthreads();
    float mu = red[0] * (1.0f / DIM);
    __syncthreads();

    float4 d;
    d.x = v.x - mu; d.y = v.y - mu; d.z = v.z - mu; d.w = v.w - mu;
    float sq = d.x*d.x + d.y*d.y + d.z*d.z + d.w*d.w;
    sq = warp_sum(sq);
    if (lane == 0) red[wid] = sq;
    __syncthreads();
    if (wid == 0) {
        float t = (lane < 8) ? red[lane] : 0.f;
        t = warp_sum(t);
        if (lane == 0) red[0] = t;
    }
    __syncthreads();
    float rs = rsqrtf(red[0] * (1.0f / DIM) + 1e-5f);

    float4 g4 = reinterpret_cast<const float4*>(G)[tid];
    float4 b4 = reinterpret_cast<const float4*>(B)[tid];
    float4 y;
    y.x = d.x * rs * g4.x + b4.x;
    y.y = d.y * rs * g4.y + b4.y;
    y.z = d.z * rs * g4.z + b4.z;
    y.w = d.w * rs * g4.w + b4.w;
    reinterpret_cast<float4*>(Y + (size_t)row * DIM)[tid] = y;
}

// ---------------- generic SGEMM: C = A[M,K] @ B[K,N] (+epilogue) -----------
// epi: 0 = none, 1 = +bias, 2 = +bias then exact GELU, 3 = +bias +residual
__global__ __launch_bounds__(256) void sgemm_kernel(
    const float* __restrict__ A, const float* __restrict__ B,
    const float* __restrict__ bias, const float* __restrict__ Res,
    float* __restrict__ C, int M, int N, int K, int epi)
{
    __shared__ float As[16][132];
    __shared__ float Bs[16][128];

    int tid = threadIdx.x;
    int m0 = blockIdx.y * 128, n0 = blockIdx.x * 128;
    int tx = tid & 15, ty = tid >> 4;

    float acc[8][8];
#pragma unroll
    for (int i = 0; i < 8; i++)
#pragma unroll
        for (int j = 0; j < 8; j++) acc[i][j] = 0.f;

    int aRow = tid >> 2;            // 0..63
    int aCol = (tid & 3) * 4;       // 0,4,8,12
    int bRow = tid >> 5;            // 0..7
    int bCol = (tid & 31) * 4;      // 0..124

    for (int k0 = 0; k0 < K; k0 += 16) {
#pragma unroll
        for (int r = 0; r < 2; r++) {
            int row = aRow + r * 64;
            float4 v = *reinterpret_cast<const float4*>(
                A + (size_t)(m0 + row) * K + k0 + aCol);
            As[aCol + 0][row] = v.x; As[aCol + 1][row] = v.y;
            As[aCol + 2][row] = v.z; As[aCol + 3][row] = v.w;
        }
#pragma unroll
        for (int r = 0; r < 2; r++) {
            int row = bRow + r * 8;
            *reinterpret_cast<float4*>(&Bs[row][bCol]) =
                *reinterpret_cast<const float4*>(
                    B + (size_t)(k0 + row) * N + n0 + bCol);
        }
        __syncthreads();
#pragma unroll
        for (int k = 0; k < 16; k++) {
            float a[8], b[8];
#pragma unroll
            for (int i = 0; i < 8; i++) a[i] = As[k][ty * 8 + i];
#pragma unroll
            for (int j = 0; j < 8; j++) b[j] = Bs[k][tx * 8 + j];
#pragma unroll
            for (int i = 0; i < 8; i++)
#pragma unroll
                for (int j = 0; j < 8; j++) acc[i][j] += a[i] * b[j];
        }
        __syncthreads();
    }

#pragma unroll
    for (int i = 0; i < 8; i++) {
        int row = m0 + ty * 8 + i;
        float* crow = C + (size_t)row * N + n0 + tx * 8;
        const float* rrow = (epi == 3) ? Res + (size_t)row * N + n0 + tx * 8 : nullptr;
#pragma unroll
        for (int j = 0; j < 8; j++) {
            float c = acc[i][j];
            if (epi >= 1) c += bias[n0 + tx * 8 + j];
            if (epi == 2) c = 0.5f * c * (1.0f + erff(c * 0.70710678118654752f));
            if (epi == 3) c += rrow[j];
            crow[j] = c;
        }
    }
}

// ---------------- attention scores: S = Q @ K^T * scale --------------------
// qkv layout per row: [q(16h x 64d) | k | v], row stride 3*DIM
__global__ __launch_bounds__(256) void attn_scores_kernel(
    const float* __restrict__ qkv, float* __restrict__ S)
{
    int bh = blockIdx.z;
    int b = bh >> 4, h = bh & 15;
    const float* Q = qkv + (size_t)b * SEQ * (3 * DIM) + h * HDIM;
    const float* Kp = qkv + (size_t)b * SEQ * (3 * DIM) + DIM + h * HDIM;

    __shared__ float Qs[16][132];
    __shared__ float Ks[16][132];

    int tid = threadIdx.x;
    int m0 = blockIdx.y * 128, n0 = blockIdx.x * 128;
    int tx = tid & 15, ty = tid >> 4;

    float acc[8][8];
#pragma unroll
    for (int i = 0; i < 8; i++)
#pragma unroll
        for (int j = 0; j < 8; j++) acc[i][j] = 0.f;

    int aRow = tid >> 2;
    int aCol = (tid & 3) * 4;

    for (int k0 = 0; k0 < HDIM; k0 += 16) {
#pragma unroll
        for (int r = 0; r < 2; r++) {
            int row = aRow + r * 64;
            float4 v = *reinterpret_cast<const float4*>(
                Q + (size_t)(m0 + row) * (3 * DIM) + k0 + aCol);
            Qs[aCol + 0][row] = v.x; Qs[aCol + 1][row] = v.y;
            Qs[aCol + 2][row] = v.z; Qs[aCol + 3][row] = v.w;
            float4 w = *reinterpret_cast<const float4*>(
                Kp + (size_t)(n0 + row) * (3 * DIM) + k0 + aCol);
            Ks[aCol + 0][row] = w.x; Ks[aCol + 1][row] = w.y;
            Ks[aCol + 2][row] = w.z; Ks[aCol + 3][row] = w.w;
        }
        __syncthreads();
#pragma unroll
        for (int k = 0; k < 16; k++) {
            float a[8], bb[8];
#pragma unroll
            for (int i = 0; i < 8; i++) a[i] = Qs[k][ty * 8 + i];
#pragma unroll
            for (int j = 0; j < 8; j++) bb[j] = Ks[k][tx * 8 + j];
#pragma unroll
            for (int i = 0; i < 8; i++)
#pragma unroll
                for (int j = 0; j < 8; j++) acc[i][j] += a[i] * bb[j];
        }
        __syncthreads();
    }

    const float scale = 0.03125f;  // DIM^-0.5 = 1/32 (full dim, per reference)
    float* Sb = S + ((size_t)bh << 20);
#pragma unroll
    for (int i = 0; i < 8; i++) {
        float* srow = Sb + (size_t)(m0 + ty * 8 + i) * SEQ + n0 + tx * 8;
#pragma unroll
        for (int j = 0; j < 8; j++) srow[j] = acc[i][j] * scale;
    }
}

// ---------------- row softmax over 1024, in place --------------------------
__global__ __launch_bounds__(256) void softmax_kernel(float* __restrict__ S)
{
    __shared__ float red[8];
    size_t row = blockIdx.x;
    float* p = S + row * SEQ;
    int tid = threadIdx.x;
    int lane = tid & 31, wid = tid >> 5;

    float4 v = reinterpret_cast<float4*>(p)[tid];
    float m = fmaxf(fmaxf(v.x, v.y), fmaxf(v.z, v.w));
    m = warp_max(m);
    if (lane == 0) red[wid] = m;
    __syncthreads();
    if (wid == 0) {
        float t = (lane < 8) ? red[lane] : -1e30f;
        t = warp_max(t);
        if (lane == 0) red[0] = t;
    }
    __syncthreads();
    m = red[0];
    __syncthreads();

    float4 e;
    e.x = expf(v.x - m); e.y = expf(v.y - m);
    e.z = expf(v.z - m); e.w = expf(v.w - m);
    float s = e.x + e.y + e.z + e.w;
    s = warp_sum(s);
    if (lane == 0) red[wid] = s;
    __syncthreads();
    if (wid == 0) {
        float t = (lane < 8) ? red[lane] : 0.f;
        t = warp_sum(t);
        if (lane == 0) red[0] = t;
    }
    __syncthreads();
    float inv = 1.0f / red[0];
    e.x *= inv; e.y *= inv; e.z *= inv; e.w *= inv;
    reinterpret_cast<float4*>(p)[tid] = e;
}

// ---------------- PV: O_bh = P[1024,1024] @ V[1024,64] ---------------------
__global__ __launch_bounds__(256) void attn_pv_kernel(
    const float* __restrict__ S, const float* __restrict__ qkv,
    float* __restrict__ Out)
{
    int bh = blockIdx.z;
    int b = bh >> 4, h = bh & 15;
    const float* P = S + ((size_t)bh << 20);
    const float* V = qkv + (size_t)b * SEQ * (3 * DIM) + 2 * DIM + h * HDIM;

    __shared__ float Ps[32][132];
    __shared__ float Vs[32][64];

    int tid = threadIdx.x;
    int m0 = blockIdx.y * 128;
    int tx = tid & 15, ty = tid >> 4;

    float acc[8][4];
#pragma unroll
    for (int i = 0; i < 8; i++)
#pragma unroll
        for (int j = 0; j < 4; j++) acc[i][j] = 0.f;

    int pRow = tid >> 3;            // 0..31
    int pCol = (tid & 7) * 4;       // 0..28
    int vRow = tid >> 4;            // 0..15
    int vCol = (tid & 15) * 4;      // 0..60

    for (int k0 = 0; k0 < SEQ; k0 += 32) {
#pragma unroll
        for (int r = 0; r < 4; r++) {
            int row = pRow + r * 32;
            float4 v = *reinterpret_cast<const float4*>(
                P + (size_t)(m0 + row) * SEQ + k0 + pCol);
            Ps[pCol + 0][row] = v.x; Ps[pCol + 1][row] = v.y;
            Ps[pCol + 2][row] = v.z; Ps[pCol + 3][row] = v.w;
        }
#pragma unroll
        for (int r = 0; r < 2; r++) {
            int row = vRow + r * 16;
            *reinterpret_cast<float4*>(&Vs[row][vCol]) =
                *reinterpret_cast<const float4*>(
                    V + (size_t)(k0 + row) * (3 * DIM) + vCol);
        }
        __syncthreads();
#pragma unroll
        for (int k = 0; k < 32; k++) {
            float a[8];
#pragma unroll
            for (int i = 0; i < 8; i++) a[i] = Ps[k][ty * 8 + i];
            float4 bv = *reinterpret_cast<const float4*>(&Vs[k][tx * 4]);
#pragma unroll
            for (int i = 0; i < 8; i++) {
                acc[i][0] += a[i] * bv.x;
                acc[i][1] += a[i] * bv.y;
                acc[i][2] += a[i] * bv.z;
                acc[i][3] += a[i] * bv.w;
            }
        }
        __syncthreads();
    }

#pragma unroll
    for (int i = 0; i < 8; i++) {
        float* orow = Out + (size_t)(b * SEQ + m0 + ty * 8 + i) * DIM + h * HDIM + tx * 4;
#pragma unroll
        for (int j = 0; j < 4; j++) orow[j] = acc[i][j];
    }
}

// ---------------- copy ----------------
__global__ void copy4_kernel(const float4* __restrict__ s, float4* __restrict__ d, int n4)
{
    int i = blockIdx.x * blockDim.x + threadIdx.x;
    if (i < n4) d[i] = s[i];
}

// ---------------- launch ----------------
extern "C" void kernel_launch(void* const* d_in, const int* in_sizes, int n_in,
                              void* d_out, int out_size)
{
    const float* x     = (const float*)d_in[0];
    const float* ln1_g = (const float*)d_in[1];
    const float* ln1_b = (const float*)d_in[2];
    const float* w_qkv = (const float*)d_in[3];
    const float* w_o   = (const float*)d_in[4];
    const float* b_o   = (const float*)d_in[5];
    const float* ln2_g = (const float*)d_in[6];
    const float* ln2_b = (const float*)d_in[7];
    const float* w1    = (const float*)d_in[8];
    const float* b1    = (const float*)d_in[9];
    const float* w2    = (const float*)d_in[10];
    const float* b2    = (const float*)d_in[11];

    float *gx, *gxn, *gqkv, *gs, *gattn, *gh;
    cudaGetSymbolAddress((void**)&gx,    g_x);
    cudaGetSymbolAddress((void**)&gxn,   g_xn);
    cudaGetSymbolAddress((void**)&gqkv,  g_qkv);
    cudaGetSymbolAddress((void**)&gs,    g_s);
    cudaGetSymbolAddress((void**)&gattn, g_attn);
    cudaGetSymbolAddress((void**)&gh,    g_h);

    // x -> g_x
    copy4_kernel<<<(RTOK * DIM / 4 + 255) / 256, 256>>>(
        (const float4*)x, (float4*)gx, RTOK * DIM / 4);

    for (int layer = 0; layer < 4; layer++) {
        // --- attention block ---
        ln_kernel<<<RTOK, 256>>>(gx, ln1_g, ln1_b, gxn);
        sgemm_kernel<<<dim3(3 * DIM / 128, RTOK / 128), 256>>>(
            gxn, w_qkv, nullptr, nullptr, gqkv, RTOK, 3 * DIM, DIM, 0);
        attn_scores_kernel<<<dim3(SEQ / 128, SEQ / 128, NBH), 256>>>(gqkv, gs);
        softmax_kernel<<<NBH * SEQ, 256>>>(gs);
        attn_pv_kernel<<<dim3(1, SEQ / 128, NBH), 256>>>(gs, gqkv, gattn);
        sgemm_kernel<<<dim3(DIM / 128, RTOK / 128), 256>>>(
            gattn, w_o, b_o, gx, gx, RTOK, DIM, DIM, 3);

        // --- MLP block ---
        ln_kernel<<<RTOK, 256>>>(gx, ln2_g, ln2_b, gxn);
        sgemm_kernel<<<dim3(MLPD / 128, RTOK / 128), 256>>>(
            gxn, w1, b1, nullptr, gh, RTOK, MLPD, DIM, 2);
        sgemm_kernel<<<dim3(DIM / 128, RTOK / 128), 256>>>(
            gh, w2, b2, gx, gx, RTOK, DIM, MLPD, 3);
    }

    // g_x -> out
    copy4_kernel<<<(RTOK * DIM / 4 + 255) / 256, 256>>>(
        (const float4*)gx, (float4*)d_out, RTOK * DIM / 4);
}

// round 3
// speedup vs baseline: 2.4361x; 2.4361x over previous
#include <cuda_runtime.h>
#include <cuda_bf16.h>
#include <math.h>
#include <stdint.h>

#define RTOK 2048
#define DIM  1024
#define NH   16
#define HDIM 64
#define MLPD 4096
#define NBH  32
#define SEQ  1024

// ------------------------- scratch (device globals) -------------------------
__device__ float g_x  [RTOK * DIM];
__device__ float g_qkv[RTOK * 3 * DIM];
__device__ float g_s  [(size_t)NBH * SEQ * SEQ];
// packed (SW128-swizzled 16KB-block) bf16 operands, hi/lo splits
__device__ __align__(128) __nv_bfloat16 g_a0[RTOK * DIM],  g_a1[RTOK * DIM];
__device__ __align__(128) __nv_bfloat16 g_h0[RTOK * MLPD], g_h1[RTOK * MLPD];
__device__ __align__(128) __nv_bfloat16 g_wq0[3*DIM*DIM], g_wq1[3*DIM*DIM];
__device__ __align__(128) __nv_bfloat16 g_wo0[DIM*DIM],   g_wo1[DIM*DIM];
__device__ __align__(128) __nv_bfloat16 g_w10[MLPD*DIM],  g_w11[MLPD*DIM];
__device__ __align__(128) __nv_bfloat16 g_w20[DIM*MLPD],  g_w21[DIM*MLPD];

// ------------------------- helpers -------------------------
__device__ __forceinline__ uint32_t smem_u32(const void* p) {
    uint32_t a;
    asm("{ .reg .u64 t; cvta.to.shared.u64 t, %1; cvt.u32.u64 %0, t; }" : "=r"(a) : "l"(p));
    return a;
}
__device__ __forceinline__ uint32_t sw128(uint32_t off) { return off ^ ((off >> 3) & 0x70); }

// byte offset of (row, col) in packed layout: blocks of [128 rows x 64 bf16cols],
// blocks along k contiguous per row-block, SW128 swizzle inside a block.
__device__ __forceinline__ size_t packed_off(int row, int col, int K) {
    int rb = row >> 7, kc = col >> 6;
    uint32_t off = ((uint32_t)(row & 127) << 7) | ((uint32_t)(col & 63) << 1);
    off = off ^ ((off >> 3) & 0x70);
    return ((size_t)(rb * (K >> 6) + kc) << 14) + off;
}

__device__ __forceinline__ void mbar_init(uint32_t a, uint32_t cnt) {
    asm volatile("mbarrier.init.shared.b64 [%0], %1;" :: "r"(a), "r"(cnt) : "memory");
}
__device__ __forceinline__ void mbar_expect_tx(uint32_t a, uint32_t bytes) {
    asm volatile("mbarrier.arrive.expect_tx.shared.b64 _, [%0], %1;" :: "r"(a), "r"(bytes) : "memory");
}
__device__ __forceinline__ void mbar_wait(uint32_t a, uint32_t parity) {
    asm volatile(
        "{\n\t.reg .pred P1;\n\t"
        "LAB_WAIT_%=:\n\t"
        "mbarrier.try_wait.parity.acquire.cta.shared::cta.b64 P1, [%0], %1, 0x989680;\n\t"
        "@P1 bra.uni LAB_DONE_%=;\n\t"
        "bra.uni LAB_WAIT_%=;\n\t"
        "LAB_DONE_%=:\n\t}"
        :: "r"(a), "r"(parity) : "memory");
}
__device__ __forceinline__ void bulk_g2s(uint32_t dst, const void* src, uint32_t bytes, uint32_t mbar) {
    asm volatile(
        "cp.async.bulk.shared::cta.global.mbarrier::complete_tx::bytes [%0], [%1], %2, [%3];"
        :: "r"(dst), "l"(src), "r"(bytes), "r"(mbar) : "memory");
}
__device__ __forceinline__ void ldsm4(uint32_t* r, uint32_t addr) {
    asm volatile("ldmatrix.sync.aligned.m8n8.x4.shared.b16 {%0,%1,%2,%3}, [%4];"
                 : "=r"(r[0]), "=r"(r[1]), "=r"(r[2]), "=r"(r[3]) : "r"(addr));
}
__device__ __forceinline__ void mma16816(float* c, const uint32_t* a, const uint32_t* b) {
    asm volatile(
        "mma.sync.aligned.m16n8k16.row.col.f32.bf16.bf16.f32 "
        "{%0,%1,%2,%3}, {%4,%5,%6,%7}, {%8,%9}, {%0,%1,%2,%3};"
        : "+f"(c[0]), "+f"(c[1]), "+f"(c[2]), "+f"(c[3])
        : "r"(a[0]), "r"(a[1]), "r"(a[2]), "r"(a[3]), "r"(b[0]), "r"(b[1]));
}

#define TILE_BYTES  16384
#define STAGE_BYTES 65536
#define SM_TILES    1024
#define SM_TOTAL    (SM_TILES + 2 * STAGE_BYTES)

// ------------------------- bf16-split tensor GEMM (mma.sync) -------------------------
// C[M,N] = (A0+A1)[M,K] @ (B0+B1)^T, A/B in packed layout ([rows,K] logical).
// epi: 0 = fp32 out; 1 = +bias +Res -> fp32; 2 = +bias, GELU -> packed bf16 splits
__global__ __launch_bounds__(256, 1) void gemm_tc(
    const char* __restrict__ A0, const char* __restrict__ A1,
    const char* __restrict__ B0, const char* __restrict__ B1,
    const float* __restrict__ bias, const float* __restrict__ Res,
    float* __restrict__ Cf, char* __restrict__ C0, char* __restrict__ C1,
    int N, int K, int epi)
{
    extern __shared__ char smem[];
    uint32_t sb = smem_u32(smem);
    int tid = threadIdx.x, wid = tid >> 5, lane = tid & 31;
    int m0 = blockIdx.y * 128, n0 = blockIdx.x * 128;
    int warp_m = (wid >> 1) * 32, warp_n = (wid & 1) * 64;
    const int NC = K >> 6;

    if (tid == 0) { mbar_init(sb, 1); mbar_init(sb + 8, 1); }
    __syncthreads();

    size_t abase = ((size_t)((m0 >> 7) * NC)) << 14;
    size_t bbase = ((size_t)((n0 >> 7) * NC)) << 14;

    auto load_chunk = [&](int c, int s) {
        uint32_t mb = sb + s * 8;
        uint32_t dst = sb + SM_TILES + s * STAGE_BYTES;
        size_t go = (size_t)c << 14;
        mbar_expect_tx(mb, STAGE_BYTES);
        bulk_g2s(dst,                 A0 + abase + go, TILE_BYTES, mb);
        bulk_g2s(dst + TILE_BYTES,    A1 + abase + go, TILE_BYTES, mb);
        bulk_g2s(dst + 2*TILE_BYTES,  B0 + bbase + go, TILE_BYTES, mb);
        bulk_g2s(dst + 3*TILE_BYTES,  B1 + bbase + go, TILE_BYTES, mb);
    };

    if (tid == 0) load_chunk(0, 0);

    float acc[2][8][4];
#pragma unroll
    for (int i = 0; i < 2; i++)
#pragma unroll
        for (int j = 0; j < 8; j++)
#pragma unroll
            for (int q = 0; q < 4; q++) acc[i][j][q] = 0.f;

    // per-lane ldmatrix address components
    int a_row = warp_m + (lane & 15);
    int a_ks  = (lane >> 4) << 4;            // 0 or 16 bytes
    int b_nr  = warp_n + ((lane >> 4) << 3) + (lane & 7);
    int b_ks  = ((lane >> 3) & 1) << 4;      // 0 or 16 bytes

    for (int c = 0; c < NC; c++) {
        int s = c & 1;
        mbar_wait(sb + s * 8, (c >> 1) & 1);
        if (tid == 0 && c + 1 < NC) load_chunk(c + 1, s ^ 1);

        uint32_t base = sb + SM_TILES + s * STAGE_BYTES;
#pragma unroll
        for (int ks = 0; ks < 4; ks++) {
            uint32_t aA[2][2][4];
#pragma unroll
            for (int mi = 0; mi < 2; mi++) {
                uint32_t off = sw128((uint32_t)(a_row + mi * 16) * 128 + ks * 32 + a_ks);
                ldsm4(aA[mi][0], base + off);
                ldsm4(aA[mi][1], base + TILE_BYTES + off);
            }
#pragma unroll
            for (int nj = 0; nj < 4; nj++) {
                uint32_t boff = sw128((uint32_t)(b_nr + nj * 16) * 128 + ks * 32 + b_ks);
                uint32_t b0[4], b1[4];
                ldsm4(b0, base + 2 * TILE_BYTES + boff);
                ldsm4(b1, base + 3 * TILE_BYTES + boff);
#pragma unroll
                for (int mi = 0; mi < 2; mi++) {
#pragma unroll
                    for (int nf = 0; nf < 2; nf++) {
                        float* cc = acc[mi][nj * 2 + nf];
                        mma16816(cc, aA[mi][0], b0 + 2 * nf);
                        mma16816(cc, aA[mi][0], b1 + 2 * nf);
                        mma16816(cc, aA[mi][1], b0 + 2 * nf);
                    }
                }
            }
        }
        __syncthreads();
    }

    // ---- epilogue from register fragments ----
    int mrow = m0 + warp_m + (lane >> 2);
    int ncol = n0 + warp_n + (lane & 3) * 2;
#pragma unroll
    for (int mi = 0; mi < 2; mi++) {
#pragma unroll
        for (int nj = 0; nj < 8; nj++) {
#pragma unroll
            for (int h = 0; h < 2; h++) {
                int m = mrow + mi * 16 + h * 8;
                int n = ncol + nj * 8;
                float v0 = acc[mi][nj][2 * h];
                float v1 = acc[mi][nj][2 * h + 1];
                if (epi == 0) {
                    *reinterpret_cast<float2*>(Cf + (size_t)m * N + n) = make_float2(v0, v1);
                } else if (epi == 1) {
                    size_t off = (size_t)m * N + n;
                    float2 r = *reinterpret_cast<const float2*>(Res + off);
                    *reinterpret_cast<float2*>(Cf + off) =
                        make_float2(v0 + bias[n] + r.x, v1 + bias[n + 1] + r.y);
                } else {
                    float t0 = v0 + bias[n],     t1 = v1 + bias[n + 1];
                    float g0 = 0.5f * t0 * (1.0f + erff(t0 * 0.70710678118654752f));
                    float g1 = 0.5f * t1 * (1.0f + erff(t1 * 0.70710678118654752f));
                    __nv_bfloat16 h0 = __float2bfloat16(g0);
                    __nv_bfloat16 h1 = __float2bfloat16(g1);
                    __nv_bfloat162 hip = __nv_bfloat162(h0, h1);
                    __nv_bfloat162 lop = __nv_bfloat162(
                        __float2bfloat16(g0 - __bfloat162float(h0)),
                        __float2bfloat16(g1 - __bfloat162float(h1)));
                    size_t po = packed_off(m, n, N);
                    *reinterpret_cast<__nv_bfloat162*>(C0 + po) = hip;
                    *reinterpret_cast<__nv_bfloat162*>(C1 + po) = lop;
                }
            }
        }
    }
}

// ------------------------- reductions -------------------------
__device__ __forceinline__ float warp_sum(float v) {
#pragma unroll
    for (int o = 16; o; o >>= 1) v += __shfl_xor_sync(0xffffffffu, v, o);
    return v;
}
__device__ __forceinline__ float warp_max(float v) {
#pragma unroll
    for (int o = 16; o; o >>= 1) v = fmaxf(v, __shfl_xor_sync(0xffffffffu, v, o));
    return v;
}

// ------------------------- layernorm -> packed bf16 splits -------------------------
__global__ __launch_bounds__(256) void ln_split_kernel(
    const float* __restrict__ X, const float* __restrict__ G,
    const float* __restrict__ B, char* __restrict__ Y0, char* __restrict__ Y1)
{
    __shared__ float red[8];
    int row = blockIdx.x;
    int tid = threadIdx.x;
    int lane = tid & 31, wid = tid >> 5;

    float4 v = reinterpret_cast<const float4*>(X + (size_t)row * DIM)[tid];
    float s = v.x + v.y + v.z + v.w;
    s = warp_sum(s);
    if (lane == 0) red[wid] = s;
    __syncthreads();
    if (wid == 0) {
        float t = (lane < 8) ? red[lane] : 0.f;
        t = warp_sum(t);
        if (lane == 0) red[0] = t;
    }
    __syncthreads();
    float mu = red[0] * (1.0f / DIM);
    __syncthreads();

    float4 d;
    d.x = v.x - mu; d.y = v.y - mu; d.z = v.z - mu; d.w = v.w - mu;
    float sq = d.x*d.x + d.y*d.y + d.z*d.z + d.w*d.w;
    sq = warp_sum(sq);
    if (lane == 0) red[wid] = sq;
    __syncthreads();
    if (wid == 0) {
        float t = (lane < 8) ? red[lane] : 0.f;
        t = warp_sum(t);
        if (lane == 0) red[0] = t;
    }
    __syncthreads();
    float rs = rsqrtf(red[0] * (1.0f / DIM) + 1e-5f);

    float4 g4 = reinterpret_cast<const float4*>(G)[tid];
    float4 b4 = reinterpret_cast<const float4*>(B)[tid];
    float y[4];
    y[0] = d.x * rs * g4.x + b4.x;
    y[1] = d.y * rs * g4.y + b4.y;
    y[2] = d.z * rs * g4.z + b4.z;
    y[3] = d.w * rs * g4.w + b4.w;

    __nv_bfloat16 hi[4], lo[4];
#pragma unroll
    for (int q = 0; q < 4; q++) {
        hi[q] = __float2bfloat16(y[q]);
        lo[q] = __float2bfloat16(y[q] - __bfloat162float(hi[q]));
    }
    size_t po = packed_off(row, tid * 4, DIM);
    *reinterpret_cast<uint2*>(Y0 + po) = *reinterpret_cast<uint2*>(hi);
    *reinterpret_cast<uint2*>(Y1 + po) = *reinterpret_cast<uint2*>(lo);
}

// ------------------------- attention scores (scalar fp32) -------------------------
__global__ __launch_bounds__(256) void attn_scores_kernel(
    const float* __restrict__ qkv, float* __restrict__ S)
{
    int bh = blockIdx.z;
    int b = bh >> 4, h = bh & 15;
    const float* Q  = qkv + (size_t)b * SEQ * (3 * DIM) + h * HDIM;
    const float* Kp = qkv + (size_t)b * SEQ * (3 * DIM) + DIM + h * HDIM;

    __shared__ float Qs[16][132];
    __shared__ float Ks[16][132];

    int tid = threadIdx.x;
    int m0 = blockIdx.y * 128, n0 = blockIdx.x * 128;
    int tx = tid & 15, ty = tid >> 4;

    float acc[8][8];
#pragma unroll
    for (int i = 0; i < 8; i++)
#pragma unroll
        for (int j = 0; j < 8; j++) acc[i][j] = 0.f;

    int aRow = tid >> 2;
    int aCol = (tid & 3) * 4;

    for (int k0 = 0; k0 < HDIM; k0 += 16) {
#pragma unroll
        for (int r = 0; r < 2; r++) {
            int row = aRow + r * 64;
            float4 v = *reinterpret_cast<const float4*>(
                Q + (size_t)(m0 + row) * (3 * DIM) + k0 + aCol);
            Qs[aCol + 0][row] = v.x; Qs[aCol + 1][row] = v.y;
            Qs[aCol + 2][row] = v.z; Qs[aCol + 3][row] = v.w;
            float4 w = *reinterpret_cast<const float4*>(
                Kp + (size_t)(n0 + row) * (3 * DIM) + k0 + aCol);
            Ks[aCol + 0][row] = w.x; Ks[aCol + 1][row] = w.y;
            Ks[aCol + 2][row] = w.z; Ks[aCol + 3][row] = w.w;
        }
        __syncthreads();
#pragma unroll
        for (int k = 0; k < 16; k++) {
            float a[8], bb[8];
#pragma unroll
            for (int i = 0; i < 8; i++) a[i] = Qs[k][ty * 8 + i];
#pragma unroll
            for (int j = 0; j < 8; j++) bb[j] = Ks[k][tx * 8 + j];
#pragma unroll
            for (int i = 0; i < 8; i++)
#pragma unroll
                for (int j = 0; j < 8; j++) acc[i][j] += a[i] * bb[j];
        }
        __syncthreads();
    }

    const float scale = 0.03125f;
    float* Sb = S + ((size_t)bh << 20);
#pragma unroll
    for (int i = 0; i < 8; i++) {
        float* srow = Sb + (size_t)(m0 + ty * 8 + i) * SEQ + n0 + tx * 8;
#pragma unroll
        for (int j = 0; j < 8; j++) srow[j] = acc[i][j] * scale;
    }
}

// ------------------------- softmax -------------------------
__global__ __launch_bounds__(256) void softmax_kernel(float* __restrict__ S)
{
    __shared__ float red[8];
    size_t row = blockIdx.x;
    float* p = S + row * SEQ;
    int tid = threadIdx.x;
    int lane = tid & 31, wid = tid >> 5;

    float4 v = reinterpret_cast<float4*>(p)[tid];
    float m = fmaxf(fmaxf(v.x, v.y), fmaxf(v.z, v.w));
    m = warp_max(m);
    if (lane == 0) red[wid] = m;
    __syncthreads();
    if (wid == 0) {
        float t = (lane < 8) ? red[lane] : -1e30f;
        t = warp_max(t);
        if (lane == 0) red[0] = t;
    }
    __syncthreads();
    m = red[0];
    __syncthreads();

    float4 e;
    e.x = expf(v.x - m); e.y = expf(v.y - m);
    e.z = expf(v.z - m); e.w = expf(v.w - m);
    float s = e.x + e.y + e.z + e.w;
    s = warp_sum(s);
    if (lane == 0) red[wid] = s;
    __syncthreads();
    if (wid == 0) {
        float t = (lane < 8) ? red[lane] : 0.f;
        t = warp_sum(t);
        if (lane == 0) red[0] = t;
    }
    __syncthreads();
    float inv = 1.0f / red[0];
    e.x *= inv; e.y *= inv; e.z *= inv; e.w *= inv;
    reinterpret_cast<float4*>(p)[tid] = e;
}

// ------------------------- PV -> packed bf16 splits -------------------------
__global__ __launch_bounds__(256) void attn_pv_kernel(
    const float* __restrict__ S, const float* __restrict__ qkv,
    char* __restrict__ O0, char* __restrict__ O1)
{
    int bh = blockIdx.z;
    int b = bh >> 4, h = bh & 15;
    const float* P = S + ((size_t)bh << 20);
    const float* V = qkv + (size_t)b * SEQ * (3 * DIM) + 2 * DIM + h * HDIM;

    __shared__ float Ps[32][132];
    __shared__ float Vs[32][64];

    int tid = threadIdx.x;
    int m0 = blockIdx.y * 128;
    int tx = tid & 15, ty = tid >> 4;

    float acc[8][4];
#pragma unroll
    for (int i = 0; i < 8; i++)
#pragma unroll
        for (int j = 0; j < 4; j++) acc[i][j] = 0.f;

    int pRow = tid >> 3;
    int pCol = (tid & 7) * 4;
    int vRow = tid >> 4;
    int vCol = (tid & 15) * 4;

    for (int k0 = 0; k0 < SEQ; k0 += 32) {
#pragma unroll
        for (int r = 0; r < 4; r++) {
            int row = pRow + r * 32;
            float4 v = *reinterpret_cast<const float4*>(
                P + (size_t)(m0 + row) * SEQ + k0 + pCol);
            Ps[pCol + 0][row] = v.x; Ps[pCol + 1][row] = v.y;
            Ps[pCol + 2][row] = v.z; Ps[pCol + 3][row] = v.w;
        }
#pragma unroll
        for (int r = 0; r < 2; r++) {
            int row = vRow + r * 16;
            *reinterpret_cast<float4*>(&Vs[row][vCol]) =
                *reinterpret_cast<const float4*>(
                    V + (size_t)(k0 + row) * (3 * DIM) + vCol);
        }
        __syncthreads();
#pragma unroll
        for (int k = 0; k < 32; k++) {
            float a[8];
#pragma unroll
            for (int i = 0; i < 8; i++) a[i] = Ps[k][ty * 8 + i];
            float4 bv = *reinterpret_cast<const float4*>(&Vs[k][tx * 4]);
#pragma unroll
            for (int i = 0; i < 8; i++) {
                acc[i][0] += a[i] * bv.x;
                acc[i][1] += a[i] * bv.y;
                acc[i][2] += a[i] * bv.z;
                acc[i][3] += a[i] * bv.w;
            }
        }
        __syncthreads();
    }

#pragma unroll
    for (int i = 0; i < 8; i++) {
        int row = b * SEQ + m0 + ty * 8 + i;
        int col = h * HDIM + tx * 4;
        __nv_bfloat16 hi[4], lo[4];
#pragma unroll
        for (int j = 0; j < 4; j++) {
            hi[j] = __float2bfloat16(acc[i][j]);
            lo[j] = __float2bfloat16(acc[i][j] - __bfloat162float(hi[j]));
        }
        size_t po = packed_off(row, col, DIM);
        *reinterpret_cast<uint2*>(O0 + po) = *reinterpret_cast<uint2*>(hi);
        *reinterpret_cast<uint2*>(O1 + po) = *reinterpret_cast<uint2*>(lo);
    }
}

// ------------------------- weight transpose + split -> packed -------------------------
// W[K,N] fp32 -> packed [N rows, K cols] bf16 splits
__global__ __launch_bounds__(256) void wsplit_kernel(
    const float* __restrict__ W, char* __restrict__ T0, char* __restrict__ T1,
    int K, int N)
{
    __shared__ float t[32][33];
    int n0 = blockIdx.x * 32, k0 = blockIdx.y * 32;
    int c = threadIdx.x & 31, r = threadIdx.x >> 5;
#pragma unroll
    for (int rr = 0; rr < 32; rr += 8)
        t[r + rr][c] = W[(size_t)(k0 + r + rr) * N + n0 + c];
    __syncthreads();
    int tx = threadIdx.x & 7;       // k4 group
    int ty = threadIdx.x >> 3;      // n within tile
    int n = n0 + ty, k = k0 + tx * 4;
    __nv_bfloat16 hi[4], lo[4];
#pragma unroll
    for (int q = 0; q < 4; q++) {
        float v = t[tx * 4 + q][ty];
        hi[q] = __float2bfloat16(v);
        lo[q] = __float2bfloat16(v - __bfloat162float(hi[q]));
    }
    size_t po = packed_off(n, k, K);
    *reinterpret_cast<uint2*>(T0 + po) = *reinterpret_cast<uint2*>(hi);
    *reinterpret_cast<uint2*>(T1 + po) = *reinterpret_cast<uint2*>(lo);
}

// ------------------------- copy -------------------------
__global__ void copy4_kernel(const float4* __restrict__ s, float4* __restrict__ d, int n4)
{
    int i = blockIdx.x * blockDim.x + threadIdx.x;
    if (i < n4) d[i] = s[i];
}

// ------------------------- launch -------------------------
extern "C" void kernel_launch(void* const* d_in, const int* in_sizes, int n_in,
                              void* d_out, int out_size)
{
    const float* x     = (const float*)d_in[0];
    const float* ln1_g = (const float*)d_in[1];
    const float* ln1_b = (const float*)d_in[2];
    const float* w_qkv = (const float*)d_in[3];
    const float* w_o   = (const float*)d_in[4];
    const float* b_o   = (const float*)d_in[5];
    const float* ln2_g = (const float*)d_in[6];
    const float* ln2_b = (const float*)d_in[7];
    const float* w1    = (const float*)d_in[8];
    const float* b1    = (const float*)d_in[9];
    const float* w2    = (const float*)d_in[10];
    const float* b2    = (const float*)d_in[11];

    float *gx, *gqkv, *gs;
    char *a0, *a1, *h0, *h1;
    char *wq0, *wq1, *wo0, *wo1, *w10, *w11, *w20, *w21;
    cudaGetSymbolAddress((void**)&gx,   g_x);
    cudaGetSymbolAddress((void**)&gqkv, g_qkv);
    cudaGetSymbolAddress((void**)&gs,   g_s);
    cudaGetSymbolAddress((void**)&a0,   g_a0);
    cudaGetSymbolAddress((void**)&a1,   g_a1);
    cudaGetSymbolAddress((void**)&h0,   g_h0);
    cudaGetSymbolAddress((void**)&h1,   g_h1);
    cudaGetSymbolAddress((void**)&wq0,  g_wq0);
    cudaGetSymbolAddress((void**)&wq1,  g_wq1);
    cudaGetSymbolAddress((void**)&wo0,  g_wo0);
    cudaGetSymbolAddress((void**)&wo1,  g_wo1);
    cudaGetSymbolAddress((void**)&w10,  g_w10);
    cudaGetSymbolAddress((void**)&w11,  g_w11);
    cudaGetSymbolAddress((void**)&w20,  g_w20);
    cudaGetSymbolAddress((void**)&w21,  g_w21);

    cudaFuncSetAttribute(gemm_tc, cudaFuncAttributeMaxDynamicSharedMemorySize, SM_TOTAL);

    copy4_kernel<<<(RTOK * DIM / 4 + 255) / 256, 256>>>(
        (const float4*)x, (float4*)gx, RTOK * DIM / 4);
    wsplit_kernel<<<dim3(3 * DIM / 32, DIM / 32), 256>>>(w_qkv, wq0, wq1, DIM, 3 * DIM);
    wsplit_kernel<<<dim3(DIM / 32, DIM / 32), 256>>>(w_o, wo0, wo1, DIM, DIM);
    wsplit_kernel<<<dim3(MLPD / 32, DIM / 32), 256>>>(w1, w10, w11, DIM, MLPD);
    wsplit_kernel<<<dim3(DIM / 32, MLPD / 32), 256>>>(w2, w20, w21, MLPD, DIM);

    for (int layer = 0; layer < 4; layer++) {
        // --- attention ---
        ln_split_kernel<<<RTOK, 256>>>(gx, ln1_g, ln1_b, a0, a1);
        gemm_tc<<<dim3(3 * DIM / 128, RTOK / 128), 256, SM_TOTAL>>>(
            a0, a1, wq0, wq1, nullptr, nullptr, gqkv, nullptr, nullptr,
            3 * DIM, DIM, 0);
        attn_scores_kernel<<<dim3(SEQ / 128, SEQ / 128, NBH), 256>>>(gqkv, gs);
        softmax_kernel<<<NBH * SEQ, 256>>>(gs);
        attn_pv_kernel<<<dim3(1, SEQ / 128, NBH), 256>>>(gs, gqkv, a0, a1);
        gemm_tc<<<dim3(DIM / 128, RTOK / 128), 256, SM_TOTAL>>>(
            a0, a1, wo0, wo1, b_o, gx, gx, nullptr, nullptr,
            DIM, DIM, 1);

        // --- MLP ---
        ln_split_kernel<<<RTOK, 256>>>(gx, ln2_g, ln2_b, a0, a1);
        gemm_tc<<<dim3(MLPD / 128, RTOK / 128), 256, SM_TOTAL>>>(
            a0, a1, w10, w11, b1, nullptr, nullptr, h0, h1,
            MLPD, DIM, 2);
        gemm_tc<<<dim3(DIM / 128, RTOK / 128), 256, SM_TOTAL>>>(
            h0, h1, w20, w21, b2, gx, gx, nullptr, nullptr,
            DIM, MLPD, 1);
    }

    copy4_kernel<<<(RTOK * DIM / 4 + 255) / 256, 256>>>(
        (const float4*)gx, (float4*)d_out, RTOK * DIM / 4);
}

// round 4
// speedup vs baseline: 3.8703x; 1.5888x over previous
#include <cuda_runtime.h>
#include <cuda_bf16.h>
#include <math.h>
#include <stdint.h>

#define RTOK 2048
#define DIM  1024
#define NH   16
#define HDIM 64
#define MLPD 4096
#define NBH  32
#define SEQ  1024

// ------------------------- scratch (device globals) -------------------------
__device__ float g_x[RTOK * DIM];
__device__ __align__(128) __nv_bfloat16 g_a0[RTOK * DIM],  g_a1[RTOK * DIM];
__device__ __align__(128) __nv_bfloat16 g_h0[RTOK * MLPD], g_h1[RTOK * MLPD];
__device__ __align__(128) __nv_bfloat16 g_q0[RTOK * DIM],  g_q1[RTOK * DIM];
__device__ __align__(128) __nv_bfloat16 g_k0[RTOK * DIM],  g_k1[RTOK * DIM];
__device__ __align__(128) __nv_bfloat16 g_v0[RTOK * DIM],  g_v1[RTOK * DIM];
__device__ __align__(128) __nv_bfloat16 g_wq0[3*DIM*DIM], g_wq1[3*DIM*DIM];
__device__ __align__(128) __nv_bfloat16 g_wo0[DIM*DIM],   g_wo1[DIM*DIM];
__device__ __align__(128) __nv_bfloat16 g_w10[MLPD*DIM],  g_w11[MLPD*DIM];
__device__ __align__(128) __nv_bfloat16 g_w20[DIM*MLPD],  g_w21[DIM*MLPD];

// ------------------------- helpers -------------------------
__device__ __forceinline__ uint32_t smem_u32(const void* p) {
    uint32_t a;
    asm("{ .reg .u64 t; cvta.to.shared.u64 t, %1; cvt.u32.u64 %0, t; }" : "=r"(a) : "l"(p));
    return a;
}
__device__ __forceinline__ uint32_t sw128(uint32_t off) { return off ^ ((off >> 3) & 0x70); }

// packed layout: blocks of [128 rows x 64 bf16 cols] (16KB), SW128 inside block,
// blocks along K contiguous per row-block.
__device__ __forceinline__ size_t packed_off(int row, int col, int K) {
    int rb = row >> 7, kc = col >> 6;
    uint32_t off = ((uint32_t)(row & 127) << 7) | ((uint32_t)(col & 63) << 1);
    off = off ^ ((off >> 3) & 0x70);
    return ((size_t)(rb * (K >> 6) + kc) << 14) + off;
}

__device__ __forceinline__ void mbar_init(uint32_t a, uint32_t cnt) {
    asm volatile("mbarrier.init.shared.b64 [%0], %1;" :: "r"(a), "r"(cnt) : "memory");
}
__device__ __forceinline__ void mbar_expect_tx(uint32_t a, uint32_t bytes) {
    asm volatile("mbarrier.arrive.expect_tx.shared.b64 _, [%0], %1;" :: "r"(a), "r"(bytes) : "memory");
}
__device__ __forceinline__ void mbar_wait(uint32_t a, uint32_t parity) {
    asm volatile(
        "{\n\t.reg .pred P1;\n\t"
        "LAB_WAIT_%=:\n\t"
        "mbarrier.try_wait.parity.acquire.cta.shared::cta.b64 P1, [%0], %1, 0x989680;\n\t"
        "@P1 bra.uni LAB_DONE_%=;\n\t"
        "bra.uni LAB_WAIT_%=;\n\t"
        "LAB_DONE_%=:\n\t}"
        :: "r"(a), "r"(parity) : "memory");
}
__device__ __forceinline__ void bulk_g2s(uint32_t dst, const void* src, uint32_t bytes, uint32_t mbar) {
    asm volatile(
        "cp.async.bulk.shared::cta.global.mbarrier::complete_tx::bytes [%0], [%1], %2, [%3];"
        :: "r"(dst), "l"(src), "r"(bytes), "r"(mbar) : "memory");
}
__device__ __forceinline__ void ldsm4(uint32_t* r, uint32_t addr) {
    asm volatile("ldmatrix.sync.aligned.m8n8.x4.shared.b16 {%0,%1,%2,%3}, [%4];"
                 : "=r"(r[0]), "=r"(r[1]), "=r"(r[2]), "=r"(r[3]) : "r"(addr));
}
__device__ __forceinline__ void ldsm4t(uint32_t* r, uint32_t addr) {
    asm volatile("ldmatrix.sync.aligned.m8n8.x4.trans.shared.b16 {%0,%1,%2,%3}, [%4];"
                 : "=r"(r[0]), "=r"(r[1]), "=r"(r[2]), "=r"(r[3]) : "r"(addr));
}
__device__ __forceinline__ void mma16816(float* c, const uint32_t* a, const uint32_t* b) {
    asm volatile(
        "mma.sync.aligned.m16n8k16.row.col.f32.bf16.bf16.f32 "
        "{%0,%1,%2,%3}, {%4,%5,%6,%7}, {%8,%9}, {%0,%1,%2,%3};"
        : "+f"(c[0]), "+f"(c[1]), "+f"(c[2]), "+f"(c[3])
        : "r"(a[0]), "r"(a[1]), "r"(a[2]), "r"(a[3]), "r"(b[0]), "r"(b[1]));
}
__device__ __forceinline__ float ex2(float x) {
    float y; asm("ex2.approx.f32 %0, %1;" : "=f"(y) : "f"(x)); return y;
}
__device__ __forceinline__ uint32_t bpack_hi(float x, float y) {
    __nv_bfloat162 t(__float2bfloat16(x), __float2bfloat16(y));
    return *reinterpret_cast<uint32_t*>(&t);
}
__device__ __forceinline__ uint32_t bpack_lo(float x, float y) {
    __nv_bfloat16 hx = __float2bfloat16(x), hy = __float2bfloat16(y);
    __nv_bfloat162 t(__float2bfloat16(x - __bfloat162float(hx)),
                     __float2bfloat16(y - __bfloat162float(hy)));
    return *reinterpret_cast<uint32_t*>(&t);
}

#define TILE_BYTES  16384
#define STAGE_BYTES 65536
#define SM_TILES    1024
#define SM_TOTAL    (SM_TILES + 2 * STAGE_BYTES)

// ------------------------- bf16-split tensor GEMM (mma.sync) -------------------------
// C = (A0+A1)[M,K] @ (B0+B1)^T, packed operands.
// epi: 0 fp32 out; 1 +bias+Res fp32; 2 +bias GELU -> packed splits; 3 QKV -> packed splits per head
__global__ __launch_bounds__(256, 1) void gemm_tc(
    const char* __restrict__ A0, const char* __restrict__ A1,
    const char* __restrict__ B0, const char* __restrict__ B1,
    const float* __restrict__ bias, const float* __restrict__ Res,
    float* __restrict__ Cf, char* __restrict__ C0, char* __restrict__ C1,
    char* __restrict__ K0o, char* __restrict__ K1o,
    char* __restrict__ V0o, char* __restrict__ V1o,
    int N, int K, int epi)
{
    extern __shared__ char smem[];
    uint32_t sb = smem_u32(smem);
    int tid = threadIdx.x, wid = tid >> 5, lane = tid & 31;
    int m0 = blockIdx.y * 128, n0 = blockIdx.x * 128;
    int warp_m = (wid >> 1) * 32, warp_n = (wid & 1) * 64;
    const int NC = K >> 6;

    if (tid == 0) { mbar_init(sb, 1); mbar_init(sb + 8, 1); }
    __syncthreads();

    size_t abase = ((size_t)((m0 >> 7) * NC)) << 14;
    size_t bbase = ((size_t)((n0 >> 7) * NC)) << 14;

    auto load_chunk = [&](int c, int s) {
        uint32_t mb = sb + s * 8;
        uint32_t dst = sb + SM_TILES + s * STAGE_BYTES;
        size_t go = (size_t)c << 14;
        mbar_expect_tx(mb, STAGE_BYTES);
        bulk_g2s(dst,                 A0 + abase + go, TILE_BYTES, mb);
        bulk_g2s(dst + TILE_BYTES,    A1 + abase + go, TILE_BYTES, mb);
        bulk_g2s(dst + 2*TILE_BYTES,  B0 + bbase + go, TILE_BYTES, mb);
        bulk_g2s(dst + 3*TILE_BYTES,  B1 + bbase + go, TILE_BYTES, mb);
    };

    if (tid == 0) load_chunk(0, 0);

    float acc[2][8][4];
#pragma unroll
    for (int i = 0; i < 2; i++)
#pragma unroll
        for (int j = 0; j < 8; j++)
#pragma unroll
            for (int q = 0; q < 4; q++) acc[i][j][q] = 0.f;

    int a_row = warp_m + (lane & 15);
    int a_ks  = (lane >> 4) << 4;
    int b_nr  = warp_n + ((lane >> 4) << 3) + (lane & 7);
    int b_ks  = ((lane >> 3) & 1) << 4;

    for (int c = 0; c < NC; c++) {
        int s = c & 1;
        mbar_wait(sb + s * 8, (c >> 1) & 1);
        if (tid == 0 && c + 1 < NC) load_chunk(c + 1, s ^ 1);

        uint32_t base = sb + SM_TILES + s * STAGE_BYTES;
#pragma unroll
        for (int ks = 0; ks < 4; ks++) {
            uint32_t aA[2][2][4];
#pragma unroll
            for (int mi = 0; mi < 2; mi++) {
                uint32_t off = sw128((uint32_t)(a_row + mi * 16) * 128 + ks * 32 + a_ks);
                ldsm4(aA[mi][0], base + off);
                ldsm4(aA[mi][1], base + TILE_BYTES + off);
            }
#pragma unroll
            for (int nj = 0; nj < 4; nj++) {
                uint32_t boff = sw128((uint32_t)(b_nr + nj * 16) * 128 + ks * 32 + b_ks);
                uint32_t b0[4], b1[4];
                ldsm4(b0, base + 2 * TILE_BYTES + boff);
                ldsm4(b1, base + 3 * TILE_BYTES + boff);
#pragma unroll
                for (int mi = 0; mi < 2; mi++) {
#pragma unroll
                    for (int nf = 0; nf < 2; nf++) {
                        float* cc = acc[mi][nj * 2 + nf];
                        mma16816(cc, aA[mi][0], b0 + 2 * nf);
                        mma16816(cc, aA[mi][0], b1 + 2 * nf);
                        mma16816(cc, aA[mi][1], b0 + 2 * nf);
                    }
                }
            }
        }
        __syncthreads();
    }

    int mrow = m0 + warp_m + (lane >> 2);
    int ncol = n0 + warp_n + (lane & 3) * 2;
#pragma unroll
    for (int mi = 0; mi < 2; mi++) {
#pragma unroll
        for (int nj = 0; nj < 8; nj++) {
#pragma unroll
            for (int h = 0; h < 2; h++) {
                int m = mrow + mi * 16 + h * 8;
                int n = ncol + nj * 8;
                float v0 = acc[mi][nj][2 * h];
                float v1 = acc[mi][nj][2 * h + 1];
                if (epi == 0) {
                    *reinterpret_cast<float2*>(Cf + (size_t)m * N + n) = make_float2(v0, v1);
                } else if (epi == 1) {
                    size_t off = (size_t)m * N + n;
                    float2 r = *reinterpret_cast<const float2*>(Res + off);
                    *reinterpret_cast<float2*>(Cf + off) =
                        make_float2(v0 + bias[n] + r.x, v1 + bias[n + 1] + r.y);
                } else if (epi == 2) {
                    float t0 = v0 + bias[n],     t1 = v1 + bias[n + 1];
                    float g0 = 0.5f * t0 * (1.0f + erff(t0 * 0.70710678118654752f));
                    float g1 = 0.5f * t1 * (1.0f + erff(t1 * 0.70710678118654752f));
                    size_t po = packed_off(m, n, N);
                    *reinterpret_cast<uint32_t*>(C0 + po) = bpack_hi(g0, g1);
                    *reinterpret_cast<uint32_t*>(C1 + po) = bpack_lo(g0, g1);
                } else {
                    // QKV split per head: n -> (sel, head, d)
                    int sel = n >> 10;
                    int hh  = (n >> 6) & 15;
                    int d   = n & 63;
                    int bb  = m >> 10;
                    int qq  = m & 1023;
                    int blk = ((bb * 16 + hh) * 8) + (qq >> 7);
                    uint32_t off = (uint32_t)(qq & 127) * 128 + d * 2;
                    off ^= (off >> 3) & 0x70;
                    size_t po = ((size_t)blk << 14) + off;
                    char* D0 = (sel == 0) ? C0 : (sel == 1) ? K0o : V0o;
                    char* D1 = (sel == 0) ? C1 : (sel == 1) ? K1o : V1o;
                    *reinterpret_cast<uint32_t*>(D0 + po) = bpack_hi(v0, v1);
                    *reinterpret_cast<uint32_t*>(D1 + po) = bpack_lo(v0, v1);
                }
            }
        }
    }
}

// ------------------------- flash attention -------------------------
// grid (8, 32): x = q block, y = bh.  256 threads, 8 warps x 16 q-rows.
#define FL_SMQ   1024
#define FL_SMKV  (1024 + 32768)
#define FL_TOTAL (1024 + 32768 + 2 * 65536)

__global__ __launch_bounds__(256, 1) void flash_kernel(
    const char* __restrict__ Q0, const char* __restrict__ Q1,
    const char* __restrict__ K0, const char* __restrict__ K1,
    const char* __restrict__ V0, const char* __restrict__ V1,
    char* __restrict__ O0, char* __restrict__ O1)
{
    extern __shared__ char smem[];
    uint32_t sb = smem_u32(smem);
    int tid = threadIdx.x, wid = tid >> 5, lane = tid & 31;
    int qb = blockIdx.x, bh = blockIdx.y;
    const float SCALE_LOG2E = 0.03125f * 1.44269504088896341f;

    if (tid == 0) { mbar_init(sb, 1); mbar_init(sb + 8, 1); mbar_init(sb + 16, 1); }
    __syncthreads();

    auto load_chunk = [&](int j, int s) {
        uint32_t mb = sb + s * 8;
        uint32_t dst = sb + FL_SMKV + s * 65536;
        size_t go = ((size_t)(bh * 8 + j)) << 14;
        mbar_expect_tx(mb, 65536);
        bulk_g2s(dst,         K0 + go, TILE_BYTES, mb);
        bulk_g2s(dst + 16384, K1 + go, TILE_BYTES, mb);
        bulk_g2s(dst + 32768, V0 + go, TILE_BYTES, mb);
        bulk_g2s(dst + 49152, V1 + go, TILE_BYTES, mb);
    };

    if (tid == 0) {
        size_t qo = ((size_t)(bh * 8 + qb)) << 14;
        mbar_expect_tx(sb + 16, 32768);
        bulk_g2s(sb + FL_SMQ,         Q0 + qo, TILE_BYTES, sb + 16);
        bulk_g2s(sb + FL_SMQ + 16384, Q1 + qo, TILE_BYTES, sb + 16);
        load_chunk(0, 0);
    }

    // Q fragments (hi/lo, 4 k-steps)
    mbar_wait(sb + 16, 0);
    uint32_t aQ0[4][4], aQ1[4][4];
    {
        int a_row = wid * 16 + (lane & 15);
        int a_ks  = (lane >> 4) << 4;
#pragma unroll
        for (int ks = 0; ks < 4; ks++) {
            uint32_t off = sw128((uint32_t)a_row * 128 + ks * 32 + a_ks);
            ldsm4(aQ0[ks], sb + FL_SMQ + off);
            ldsm4(aQ1[ks], sb + FL_SMQ + 16384 + off);
        }
    }

    float acc_o[8][4];
#pragma unroll
    for (int i = 0; i < 8; i++)
#pragma unroll
        for (int q = 0; q < 4; q++) acc_o[i][q] = 0.f;
    float m0 = -1e30f, m1 = -1e30f, l0 = 0.f, l1 = 0.f;

    int b_nr = (lane >> 4) * 8 + (lane & 7);
    int b_ks = ((lane >> 3) & 1) << 4;
    int v_row = lane & 15;
    int v_cs  = (lane >> 4) << 4;

    for (int j = 0; j < 8; j++) {
        int s = j & 1;
        if (tid == 0 && j + 1 < 8) load_chunk(j + 1, s ^ 1);
        mbar_wait(sb + s * 8, (j >> 1) & 1);

        uint32_t kb = sb + FL_SMKV + s * 65536;

        // ---- S = Q @ K^T ----
        float p[16][4];
#pragma unroll
        for (int i = 0; i < 16; i++)
#pragma unroll
            for (int q = 0; q < 4; q++) p[i][q] = 0.f;

#pragma unroll
        for (int nt = 0; nt < 8; nt++) {
#pragma unroll
            for (int ks = 0; ks < 4; ks++) {
                uint32_t off = sw128((uint32_t)(nt * 16 + b_nr) * 128 + ks * 32 + b_ks);
                uint32_t khi[4], klo[4];
                ldsm4(khi, kb + off);
                ldsm4(klo, kb + 16384 + off);
#pragma unroll
                for (int nf = 0; nf < 2; nf++) {
                    float* cc = p[nt * 2 + nf];
                    mma16816(cc, aQ0[ks], khi + 2 * nf);
                    mma16816(cc, aQ0[ks], klo + 2 * nf);
                    mma16816(cc, aQ1[ks], khi + 2 * nf);
                }
            }
        }

        // ---- online softmax (log2 domain) ----
        float cm0 = -1e30f, cm1 = -1e30f;
#pragma unroll
        for (int i = 0; i < 16; i++) {
            cm0 = fmaxf(cm0, fmaxf(p[i][0], p[i][1]));
            cm1 = fmaxf(cm1, fmaxf(p[i][2], p[i][3]));
        }
        cm0 = fmaxf(cm0, __shfl_xor_sync(0xffffffffu, cm0, 1));
        cm0 = fmaxf(cm0, __shfl_xor_sync(0xffffffffu, cm0, 2));
        cm1 = fmaxf(cm1, __shfl_xor_sync(0xffffffffu, cm1, 1));
        cm1 = fmaxf(cm1, __shfl_xor_sync(0xffffffffu, cm1, 2));
        float mn0 = fmaxf(m0, cm0 * SCALE_LOG2E);
        float mn1 = fmaxf(m1, cm1 * SCALE_LOG2E);
        float al0 = ex2(m0 - mn0), al1 = ex2(m1 - mn1);
        m0 = mn0; m1 = mn1;

        float sum0 = 0.f, sum1 = 0.f;
#pragma unroll
        for (int i = 0; i < 16; i++) {
            p[i][0] = ex2(p[i][0] * SCALE_LOG2E - m0); sum0 += p[i][0];
            p[i][1] = ex2(p[i][1] * SCALE_LOG2E - m0); sum0 += p[i][1];
            p[i][2] = ex2(p[i][2] * SCALE_LOG2E - m1); sum1 += p[i][2];
            p[i][3] = ex2(p[i][3] * SCALE_LOG2E - m1); sum1 += p[i][3];
        }
        sum0 += __shfl_xor_sync(0xffffffffu, sum0, 1);
        sum0 += __shfl_xor_sync(0xffffffffu, sum0, 2);
        sum1 += __shfl_xor_sync(0xffffffffu, sum1, 1);
        sum1 += __shfl_xor_sync(0xffffffffu, sum1, 2);
        l0 = al0 * l0 + sum0;
        l1 = al1 * l1 + sum1;

#pragma unroll
        for (int i = 0; i < 8; i++) {
            acc_o[i][0] *= al0; acc_o[i][1] *= al0;
            acc_o[i][2] *= al1; acc_o[i][3] *= al1;
        }

        // ---- O += P @ V ----
        uint32_t vb = kb + 32768;
#pragma unroll
        for (int kk = 0; kk < 8; kk++) {
            uint32_t ahi[4], alo[4];
            ahi[0] = bpack_hi(p[kk*2][0],   p[kk*2][1]);
            alo[0] = bpack_lo(p[kk*2][0],   p[kk*2][1]);
            ahi[1] = bpack_hi(p[kk*2][2],   p[kk*2][3]);
            alo[1] = bpack_lo(p[kk*2][2],   p[kk*2][3]);
            ahi[2] = bpack_hi(p[kk*2+1][0], p[kk*2+1][1]);
            alo[2] = bpack_lo(p[kk*2+1][0], p[kk*2+1][1]);
            ahi[3] = bpack_hi(p[kk*2+1][2], p[kk*2+1][3]);
            alo[3] = bpack_lo(p[kk*2+1][2], p[kk*2+1][3]);
#pragma unroll
            for (int vt = 0; vt < 4; vt++) {
                uint32_t off = sw128((uint32_t)(kk * 16 + v_row) * 128 + vt * 32 + v_cs);
                uint32_t vhi[4], vlo[4];
                ldsm4t(vhi, vb + off);
                ldsm4t(vlo, vb + 16384 + off);
#pragma unroll
                for (int nf = 0; nf < 2; nf++) {
                    float* cc = acc_o[vt * 2 + nf];
                    mma16816(cc, ahi, vhi + 2 * nf);
                    mma16816(cc, ahi, vlo + 2 * nf);
                    mma16816(cc, alo, vhi + 2 * nf);
                }
            }
        }
        __syncthreads();
    }

    // ---- normalize + write packed splits ----
    float inv0 = 1.f / l0, inv1 = 1.f / l1;
    int bb = bh >> 4, hh = bh & 15;
    int grow = bb * SEQ + qb * 128 + wid * 16 + (lane >> 2);
#pragma unroll
    for (int f = 0; f < 8; f++) {
        int col = hh * 64 + f * 8 + (lane & 3) * 2;
        float x0 = acc_o[f][0] * inv0, y0 = acc_o[f][1] * inv0;
        float x1 = acc_o[f][2] * inv1, y1 = acc_o[f][3] * inv1;
        size_t po0 = packed_off(grow, col, DIM);
        size_t po1 = packed_off(grow + 8, col, DIM);
        *reinterpret_cast<uint32_t*>(O0 + po0) = bpack_hi(x0, y0);
        *reinterpret_cast<uint32_t*>(O1 + po0) = bpack_lo(x0, y0);
        *reinterpret_cast<uint32_t*>(O0 + po1) = bpack_hi(x1, y1);
        *reinterpret_cast<uint32_t*>(O1 + po1) = bpack_lo(x1, y1);
    }
}

// ------------------------- reductions -------------------------
__device__ __forceinline__ float warp_sum(float v) {
#pragma unroll
    for (int o = 16; o; o >>= 1) v += __shfl_xor_sync(0xffffffffu, v, o);
    return v;
}

// ------------------------- layernorm -> packed bf16 splits -------------------------
__global__ __launch_bounds__(256) void ln_split_kernel(
    const float* __restrict__ X, const float* __restrict__ G,
    const float* __restrict__ B, char* __restrict__ Y0, char* __restrict__ Y1)
{
    __shared__ float red[8];
    int row = blockIdx.x;
    int tid = threadIdx.x;
    int lane = tid & 31, wid = tid >> 5;

    float4 v = reinterpret_cast<const float4*>(X + (size_t)row * DIM)[tid];
    float s = v.x + v.y + v.z + v.w;
    s = warp_sum(s);
    if (lane == 0) red[wid] = s;
    __syncthreads();
    if (wid == 0) {
        float t = (lane < 8) ? red[lane] : 0.f;
        t = warp_sum(t);
        if (lane == 0) red[0] = t;
    }
    __syncthreads();
    float mu = red[0] * (1.0f / DIM);
    __syncthreads();

    float4 d;
    d.x = v.x - mu; d.y = v.y - mu; d.z = v.z - mu; d.w = v.w - mu;
    float sq = d.x*d.x + d.y*d.y + d.z*d.z + d.w*d.w;
    sq = warp_sum(sq);
    if (lane == 0) red[wid] = sq;
    __syncthreads();
    if (wid == 0) {
        float t = (lane < 8) ? red[lane] : 0.f;
        t = warp_sum(t);
        if (lane == 0) red[0] = t;
    }
    __syncthreads();
    float rs = rsqrtf(red[0] * (1.0f / DIM) + 1e-5f);

    float4 g4 = reinterpret_cast<const float4*>(G)[tid];
    float4 b4 = reinterpret_cast<const float4*>(B)[tid];
    float y[4];
    y[0] = d.x * rs * g4.x + b4.x;
    y[1] = d.y * rs * g4.y + b4.y;
    y[2] = d.z * rs * g4.z + b4.z;
    y[3] = d.w * rs * g4.w + b4.w;

    size_t po = packed_off(row, tid * 4, DIM);
    uint32_t h0 = bpack_hi(y[0], y[1]), h1 = bpack_hi(y[2], y[3]);
    uint32_t l0 = bpack_lo(y[0], y[1]), l1 = bpack_lo(y[2], y[3]);
    *reinterpret_cast<uint2*>(Y0 + po) = make_uint2(h0, h1);
    *reinterpret_cast<uint2*>(Y1 + po) = make_uint2(l0, l1);
}

// ------------------------- weight transpose + split -> packed -------------------------
__global__ __launch_bounds__(256) void wsplit_kernel(
    const float* __restrict__ W, char* __restrict__ T0, char* __restrict__ T1,
    int K, int N)
{
    __shared__ float t[32][33];
    int n0 = blockIdx.x * 32, k0 = blockIdx.y * 32;
    int c = threadIdx.x & 31, r = threadIdx.x >> 5;
#pragma unroll
    for (int rr = 0; rr < 32; rr += 8)
        t[r + rr][c] = W[(size_t)(k0 + r + rr) * N + n0 + c];
    __syncthreads();
    int tx = threadIdx.x & 7;
    int ty = threadIdx.x >> 3;
    int n = n0 + ty, k = k0 + tx * 4;
    float v0 = t[tx*4+0][ty], v1 = t[tx*4+1][ty], v2 = t[tx*4+2][ty], v3 = t[tx*4+3][ty];
    size_t po = packed_off(n, k, K);
    *reinterpret_cast<uint2*>(T0 + po) = make_uint2(bpack_hi(v0, v1), bpack_hi(v2, v3));
    *reinterpret_cast<uint2*>(T1 + po) = make_uint2(bpack_lo(v0, v1), bpack_lo(v2, v3));
}

// ------------------------- copy -------------------------
__global__ void copy4_kernel(const float4* __restrict__ s, float4* __restrict__ d, int n4)
{
    int i = blockIdx.x * blockDim.x + threadIdx.x;
    if (i < n4) d[i] = s[i];
}

// ------------------------- launch -------------------------
extern "C" void kernel_launch(void* const* d_in, const int* in_sizes, int n_in,
                              void* d_out, int out_size)
{
    const float* x     = (const float*)d_in[0];
    const float* ln1_g = (const float*)d_in[1];
    const float* ln1_b = (const float*)d_in[2];
    const float* w_qkv = (const float*)d_in[3];
    const float* w_o   = (const float*)d_in[4];
    const float* b_o   = (const float*)d_in[5];
    const float* ln2_g = (const float*)d_in[6];
    const float* ln2_b = (const float*)d_in[7];
    const float* w1    = (const float*)d_in[8];
    const float* b1    = (const float*)d_in[9];
    const float* w2    = (const float*)d_in[10];
    const float* b2    = (const float*)d_in[11];

    float *gx;
    char *a0, *a1, *h0, *h1, *q0, *q1, *k0, *k1, *v0, *v1;
    char *wq0, *wq1, *wo0, *wo1, *w10, *w11, *w20, *w21;
    cudaGetSymbolAddress((void**)&gx,  g_x);
    cudaGetSymbolAddress((void**)&a0,  g_a0);
    cudaGetSymbolAddress((void**)&a1,  g_a1);
    cudaGetSymbolAddress((void**)&h0,  g_h0);
    cudaGetSymbolAddress((void**)&h1,  g_h1);
    cudaGetSymbolAddress((void**)&q0,  g_q0);
    cudaGetSymbolAddress((void**)&q1,  g_q1);
    cudaGetSymbolAddress((void**)&k0,  g_k0);
    cudaGetSymbolAddress((void**)&k1,  g_k1);
    cudaGetSymbolAddress((void**)&v0,  g_v0);
    cudaGetSymbolAddress((void**)&v1,  g_v1);
    cudaGetSymbolAddress((void**)&wq0, g_wq0);
    cudaGetSymbolAddress((void**)&wq1, g_wq1);
    cudaGetSymbolAddress((void**)&wo0, g_wo0);
    cudaGetSymbolAddress((void**)&wo1, g_wo1);
    cudaGetSymbolAddress((void**)&w10, g_w10);
    cudaGetSymbolAddress((void**)&w11, g_w11);
    cudaGetSymbolAddress((void**)&w20, g_w20);
    cudaGetSymbolAddress((void**)&w21, g_w21);

    cudaFuncSetAttribute(gemm_tc, cudaFuncAttributeMaxDynamicSharedMemorySize, SM_TOTAL);
    cudaFuncSetAttribute(flash_kernel, cudaFuncAttributeMaxDynamicSharedMemorySize, FL_TOTAL);

    copy4_kernel<<<(RTOK * DIM / 4 + 255) / 256, 256>>>(
        (const float4*)x, (float4*)gx, RTOK * DIM / 4);
    wsplit_kernel<<<dim3(3 * DIM / 32, DIM / 32), 256>>>(w_qkv, wq0, wq1, DIM, 3 * DIM);
    wsplit_kernel<<<dim3(DIM / 32, DIM / 32), 256>>>(w_o, wo0, wo1, DIM, DIM);
    wsplit_kernel<<<dim3(MLPD / 32, DIM / 32), 256>>>(w1, w10, w11, DIM, MLPD);
    wsplit_kernel<<<dim3(DIM / 32, MLPD / 32), 256>>>(w2, w20, w21, MLPD, DIM);

    for (int layer = 0; layer < 4; layer++) {
        // --- attention ---
        ln_split_kernel<<<RTOK, 256>>>(gx, ln1_g, ln1_b, a0, a1);
        gemm_tc<<<dim3(3 * DIM / 128, RTOK / 128), 256, SM_TOTAL>>>(
            a0, a1, wq0, wq1, nullptr, nullptr, nullptr, q0, q1,
            k0, k1, v0, v1, 3 * DIM, DIM, 3);
        flash_kernel<<<dim3(8, NBH), 256, FL_TOTAL>>>(
            q0, q1, k0, k1, v0, v1, a0, a1);
        gemm_tc<<<dim3(DIM / 128, RTOK / 128), 256, SM_TOTAL>>>(
            a0, a1, wo0, wo1, b_o, gx, gx, nullptr, nullptr,
            nullptr, nullptr, nullptr, nullptr, DIM, DIM, 1);

        // --- MLP ---
        ln_split_kernel<<<RTOK, 256>>>(gx, ln2_g, ln2_b, a0, a1);
        gemm_tc<<<dim3(MLPD / 128, RTOK / 128), 256, SM_TOTAL>>>(
            a0, a1, w10, w11, b1, nullptr, nullptr, h0, h1,
            nullptr, nullptr, nullptr, nullptr, MLPD, DIM, 2);
        gemm_tc<<<dim3(DIM / 128, RTOK / 128), 256, SM_TOTAL>>>(
            h0, h1, w20, w21, b2, gx, gx, nullptr, nullptr,
            nullptr, nullptr, nullptr, nullptr, DIM, MLPD, 1);
    }

    copy4_kernel<<<(RTOK * DIM / 4 + 255) / 256, 256>>>(
        (const float4*)gx, (float4*)d_out, RTOK * DIM / 4);
}

// round 5
// speedup vs baseline: 3.9043x; 1.0088x over previous
#include <cuda_runtime.h>
#include <cuda_bf16.h>
#include <math.h>
#include <stdint.h>

#define RTOK 2048
#define DIM  1024
#define NH   16
#define HDIM 64
#define MLPD 4096
#define NBH  32
#define SEQ  1024

// ------------------------- scratch (device globals) -------------------------
__device__ float g_x[RTOK * DIM];
__device__ __align__(128) __nv_bfloat16 g_a0[RTOK * DIM],  g_a1[RTOK * DIM];
__device__ __align__(128) __nv_bfloat16 g_h0[RTOK * MLPD], g_h1[RTOK * MLPD];
__device__ __align__(128) __nv_bfloat16 g_q0[RTOK * DIM],  g_q1[RTOK * DIM];
__device__ __align__(128) __nv_bfloat16 g_k0[RTOK * DIM],  g_k1[RTOK * DIM];
__device__ __align__(128) __nv_bfloat16 g_v0[RTOK * DIM],  g_v1[RTOK * DIM];
__device__ __align__(128) __nv_bfloat16 g_wq0[3*DIM*DIM], g_wq1[3*DIM*DIM];
__device__ __align__(128) __nv_bfloat16 g_wo0[DIM*DIM],   g_wo1[DIM*DIM];
__device__ __align__(128) __nv_bfloat16 g_w10[MLPD*DIM],  g_w11[MLPD*DIM];
__device__ __align__(128) __nv_bfloat16 g_w20[DIM*MLPD],  g_w21[DIM*MLPD];

// ------------------------- helpers -------------------------
__device__ __forceinline__ uint32_t smem_u32(const void* p) {
    uint32_t a;
    asm("{ .reg .u64 t; cvta.to.shared.u64 t, %1; cvt.u32.u64 %0, t; }" : "=r"(a) : "l"(p));
    return a;
}
__device__ __forceinline__ uint32_t sw128(uint32_t off) { return off ^ ((off >> 3) & 0x70); }

__device__ __forceinline__ size_t packed_off(int row, int col, int K) {
    int rb = row >> 7, kc = col >> 6;
    uint32_t off = ((uint32_t)(row & 127) << 7) | ((uint32_t)(col & 63) << 1);
    off = off ^ ((off >> 3) & 0x70);
    return ((size_t)(rb * (K >> 6) + kc) << 14) + off;
}

__device__ __forceinline__ void mbar_init(uint32_t a, uint32_t cnt) {
    asm volatile("mbarrier.init.shared.b64 [%0], %1;" :: "r"(a), "r"(cnt) : "memory");
}
__device__ __forceinline__ void mbar_expect_tx(uint32_t a, uint32_t bytes) {
    asm volatile("mbarrier.arrive.expect_tx.shared.b64 _, [%0], %1;" :: "r"(a), "r"(bytes) : "memory");
}
__device__ __forceinline__ void mbar_wait(uint32_t a, uint32_t parity) {
    asm volatile(
        "{\n\t.reg .pred P1;\n\t"
        "LAB_WAIT_%=:\n\t"
        "mbarrier.try_wait.parity.acquire.cta.shared::cta.b64 P1, [%0], %1, 0x989680;\n\t"
        "@P1 bra.uni LAB_DONE_%=;\n\t"
        "bra.uni LAB_WAIT_%=;\n\t"
        "LAB_DONE_%=:\n\t}"
        :: "r"(a), "r"(parity) : "memory");
}
__device__ __forceinline__ void bulk_g2s(uint32_t dst, const void* src, uint32_t bytes, uint32_t mbar) {
    asm volatile(
        "cp.async.bulk.shared::cta.global.mbarrier::complete_tx::bytes [%0], [%1], %2, [%3];"
        :: "r"(dst), "l"(src), "r"(bytes), "r"(mbar) : "memory");
}
__device__ __forceinline__ void ldsm4(uint32_t* r, uint32_t addr) {
    asm volatile("ldmatrix.sync.aligned.m8n8.x4.shared.b16 {%0,%1,%2,%3}, [%4];"
                 : "=r"(r[0]), "=r"(r[1]), "=r"(r[2]), "=r"(r[3]) : "r"(addr));
}
__device__ __forceinline__ void ldsm4t(uint32_t* r, uint32_t addr) {
    asm volatile("ldmatrix.sync.aligned.m8n8.x4.trans.shared.b16 {%0,%1,%2,%3}, [%4];"
                 : "=r"(r[0]), "=r"(r[1]), "=r"(r[2]), "=r"(r[3]) : "r"(addr));
}
__device__ __forceinline__ void mma16816(float* c, const uint32_t* a, const uint32_t* b) {
    asm volatile(
        "mma.sync.aligned.m16n8k16.row.col.f32.bf16.bf16.f32 "
        "{%0,%1,%2,%3}, {%4,%5,%6,%7}, {%8,%9}, {%0,%1,%2,%3};"
        : "+f"(c[0]), "+f"(c[1]), "+f"(c[2]), "+f"(c[3])
        : "r"(a[0]), "r"(a[1]), "r"(a[2]), "r"(a[3]), "r"(b[0]), "r"(b[1]));
}
__device__ __forceinline__ float ex2(float x) {
    float y; asm("ex2.approx.f32 %0, %1;" : "=f"(y) : "f"(x)); return y;
}
__device__ __forceinline__ uint32_t bpack_hi(float x, float y) {
    __nv_bfloat162 t(__float2bfloat16(x), __float2bfloat16(y));
    return *reinterpret_cast<uint32_t*>(&t);
}
__device__ __forceinline__ uint32_t bpack_lo(float x, float y) {
    __nv_bfloat16 hx = __float2bfloat16(x), hy = __float2bfloat16(y);
    __nv_bfloat162 t(__float2bfloat16(x - __bfloat162float(hx)),
                     __float2bfloat16(y - __bfloat162float(hy)));
    return *reinterpret_cast<uint32_t*>(&t);
}

#define TILE_BYTES  16384
#define STAGE_BYTES 65536
#define SM_TILES    1024
#define NSTAGE      3
#define SM_TOTAL    (SM_TILES + NSTAGE * STAGE_BYTES)

// ------------------------- bf16-split tensor GEMM (mma.sync) -------------------------
// epi: 0 fp32 out; 1 +bias+Res fp32; 2 +bias GELU -> packed splits; 3 QKV -> packed splits per head
__global__ __launch_bounds__(256, 1) void gemm_tc(
    const char* __restrict__ A0, const char* __restrict__ A1,
    const char* __restrict__ B0, const char* __restrict__ B1,
    const float* __restrict__ bias, const float* __restrict__ Res,
    float* __restrict__ Cf, char* __restrict__ C0, char* __restrict__ C1,
    char* __restrict__ K0o, char* __restrict__ K1o,
    char* __restrict__ V0o, char* __restrict__ V1o,
    int N, int K, int epi)
{
    extern __shared__ char smem[];
    uint32_t sb = smem_u32(smem);
    int tid = threadIdx.x, wid = tid >> 5, lane = tid & 31;
    int m0 = blockIdx.y * 128, n0 = blockIdx.x * 128;
    int warp_m = (wid >> 1) * 32, warp_n = (wid & 1) * 64;
    const int NC = K >> 6;

    if (tid == 0) { mbar_init(sb, 1); mbar_init(sb + 8, 1); mbar_init(sb + 16, 1); }
    __syncthreads();

    size_t abase = ((size_t)((m0 >> 7) * NC)) << 14;
    size_t bbase = ((size_t)((n0 >> 7) * NC)) << 14;

    auto load_chunk = [&](int c, int s) {
        uint32_t mb = sb + s * 8;
        uint32_t dst = sb + SM_TILES + s * STAGE_BYTES;
        size_t go = (size_t)c << 14;
        mbar_expect_tx(mb, STAGE_BYTES);
        bulk_g2s(dst,                 A0 + abase + go, TILE_BYTES, mb);
        bulk_g2s(dst + TILE_BYTES,    A1 + abase + go, TILE_BYTES, mb);
        bulk_g2s(dst + 2*TILE_BYTES,  B0 + bbase + go, TILE_BYTES, mb);
        bulk_g2s(dst + 3*TILE_BYTES,  B1 + bbase + go, TILE_BYTES, mb);
    };

    if (tid == 0) { load_chunk(0, 0); load_chunk(1, 1); }

    float acc[2][8][4];
#pragma unroll
    for (int i = 0; i < 2; i++)
#pragma unroll
        for (int j = 0; j < 8; j++)
#pragma unroll
            for (int q = 0; q < 4; q++) acc[i][j][q] = 0.f;

    int a_row = warp_m + (lane & 15);
    int a_ks  = (lane >> 4) << 4;
    int b_nr  = warp_n + ((lane >> 4) << 3) + (lane & 7);
    int b_ks  = ((lane >> 3) & 1) << 4;

    int stage = 0, phase = 0;
    for (int c = 0; c < NC; c++) {
        mbar_wait(sb + stage * 8, phase);
        if (tid == 0 && c + 2 < NC) {
            int s2 = stage + 2; if (s2 >= NSTAGE) s2 -= NSTAGE;
            load_chunk(c + 2, s2);
        }

        uint32_t base = sb + SM_TILES + stage * STAGE_BYTES;
#pragma unroll
        for (int ks = 0; ks < 4; ks++) {
            uint32_t aA[2][2][4];
#pragma unroll
            for (int mi = 0; mi < 2; mi++) {
                uint32_t off = sw128((uint32_t)(a_row + mi * 16) * 128 + ks * 32 + a_ks);
                ldsm4(aA[mi][0], base + off);
                ldsm4(aA[mi][1], base + TILE_BYTES + off);
            }
#pragma unroll
            for (int nj = 0; nj < 4; nj++) {
                uint32_t boff = sw128((uint32_t)(b_nr + nj * 16) * 128 + ks * 32 + b_ks);
                uint32_t b0[4], b1[4];
                ldsm4(b0, base + 2 * TILE_BYTES + boff);
                ldsm4(b1, base + 3 * TILE_BYTES + boff);
#pragma unroll
                for (int mi = 0; mi < 2; mi++) {
#pragma unroll
                    for (int nf = 0; nf < 2; nf++) {
                        float* cc = acc[mi][nj * 2 + nf];
                        mma16816(cc, aA[mi][0], b0 + 2 * nf);
                        mma16816(cc, aA[mi][0], b1 + 2 * nf);
                        mma16816(cc, aA[mi][1], b0 + 2 * nf);
                    }
                }
            }
        }
        __syncthreads();
        if (++stage == NSTAGE) { stage = 0; phase ^= 1; }
    }

    int mrow = m0 + warp_m + (lane >> 2);
    int ncol = n0 + warp_n + (lane & 3) * 2;
#pragma unroll
    for (int mi = 0; mi < 2; mi++) {
#pragma unroll
        for (int nj = 0; nj < 8; nj++) {
#pragma unroll
            for (int h = 0; h < 2; h++) {
                int m = mrow + mi * 16 + h * 8;
                int n = ncol + nj * 8;
                float v0 = acc[mi][nj][2 * h];
                float v1 = acc[mi][nj][2 * h + 1];
                if (epi == 0) {
                    *reinterpret_cast<float2*>(Cf + (size_t)m * N + n) = make_float2(v0, v1);
                } else if (epi == 1) {
                    size_t off = (size_t)m * N + n;
                    float2 r = *reinterpret_cast<const float2*>(Res + off);
                    *reinterpret_cast<float2*>(Cf + off) =
                        make_float2(v0 + bias[n] + r.x, v1 + bias[n + 1] + r.y);
                } else if (epi == 2) {
                    float t0 = v0 + bias[n],     t1 = v1 + bias[n + 1];
                    float g0 = 0.5f * t0 * (1.0f + erff(t0 * 0.70710678118654752f));
                    float g1 = 0.5f * t1 * (1.0f + erff(t1 * 0.70710678118654752f));
                    size_t po = packed_off(m, n, N);
                    *reinterpret_cast<uint32_t*>(C0 + po) = bpack_hi(g0, g1);
                    *reinterpret_cast<uint32_t*>(C1 + po) = bpack_lo(g0, g1);
                } else {
                    int sel = n >> 10;
                    int hh  = (n >> 6) & 15;
                    int d   = n & 63;
                    int bb  = m >> 10;
                    int qq  = m & 1023;
                    int blk = ((bb * 16 + hh) * 8) + (qq >> 7);
                    uint32_t off = (uint32_t)(qq & 127) * 128 + d * 2;
                    off ^= (off >> 3) & 0x70;
                    size_t po = ((size_t)blk << 14) + off;
                    char* D0 = (sel == 0) ? C0 : (sel == 1) ? K0o : V0o;
                    char* D1 = (sel == 0) ? C1 : (sel == 1) ? K1o : V1o;
                    *reinterpret_cast<uint32_t*>(D0 + po) = bpack_hi(v0, v1);
                    *reinterpret_cast<uint32_t*>(D1 + po) = bpack_lo(v0, v1);
                }
            }
        }
    }
}

// ------------------------- flash attention -------------------------
// grid (8, 32): x = q block, y = bh.  256 threads, 8 warps x 16 q-rows. 3-stage KV.
#define FL_SMQ   1024
#define FL_SMKV  (1024 + 32768)
#define FL_TOTAL (1024 + 32768 + 3 * 65536)

__global__ __launch_bounds__(256, 1) void flash_kernel(
    const char* __restrict__ Q0, const char* __restrict__ Q1,
    const char* __restrict__ K0, const char* __restrict__ K1,
    const char* __restrict__ V0, const char* __restrict__ V1,
    char* __restrict__ O0, char* __restrict__ O1)
{
    extern __shared__ char smem[];
    uint32_t sb = smem_u32(smem);
    int tid = threadIdx.x, wid = tid >> 5, lane = tid & 31;
    int qb = blockIdx.x, bh = blockIdx.y;
    const float SCALE_LOG2E = 0.03125f * 1.44269504088896341f;

    if (tid == 0) {
        mbar_init(sb, 1); mbar_init(sb + 8, 1); mbar_init(sb + 16, 1); mbar_init(sb + 24, 1);
    }
    __syncthreads();

    auto load_chunk = [&](int j, int s) {
        uint32_t mb = sb + s * 8;
        uint32_t dst = sb + FL_SMKV + s * 65536;
        size_t go = ((size_t)(bh * 8 + j)) << 14;
        mbar_expect_tx(mb, 65536);
        bulk_g2s(dst,         K0 + go, TILE_BYTES, mb);
        bulk_g2s(dst + 16384, K1 + go, TILE_BYTES, mb);
        bulk_g2s(dst + 32768, V0 + go, TILE_BYTES, mb);
        bulk_g2s(dst + 49152, V1 + go, TILE_BYTES, mb);
    };

    if (tid == 0) {
        size_t qo = ((size_t)(bh * 8 + qb)) << 14;
        mbar_expect_tx(sb + 24, 32768);
        bulk_g2s(sb + FL_SMQ,         Q0 + qo, TILE_BYTES, sb + 24);
        bulk_g2s(sb + FL_SMQ + 16384, Q1 + qo, TILE_BYTES, sb + 24);
        load_chunk(0, 0);
        load_chunk(1, 1);
    }

    mbar_wait(sb + 24, 0);
    uint32_t aQ0[4][4], aQ1[4][4];
    {
        int a_row = wid * 16 + (lane & 15);
        int a_ks  = (lane >> 4) << 4;
#pragma unroll
        for (int ks = 0; ks < 4; ks++) {
            uint32_t off = sw128((uint32_t)a_row * 128 + ks * 32 + a_ks);
            ldsm4(aQ0[ks], sb + FL_SMQ + off);
            ldsm4(aQ1[ks], sb + FL_SMQ + 16384 + off);
        }
    }

    float acc_o[8][4];
#pragma unroll
    for (int i = 0; i < 8; i++)
#pragma unroll
        for (int q = 0; q < 4; q++) acc_o[i][q] = 0.f;
    float m0 = -1e30f, m1 = -1e30f, l0 = 0.f, l1 = 0.f;

    int b_nr = (lane >> 4) * 8 + (lane & 7);
    int b_ks = ((lane >> 3) & 1) << 4;
    int v_row = lane & 15;
    int v_cs  = (lane >> 4) << 4;

    int stage = 0, phase = 0;
    for (int j = 0; j < 8; j++) {
        mbar_wait(sb + stage * 8, phase);
        if (tid == 0 && j + 2 < 8) {
            int s2 = stage + 2; if (s2 >= NSTAGE) s2 -= NSTAGE;
            load_chunk(j + 2, s2);
        }

        uint32_t kb = sb + FL_SMKV + stage * 65536;

        float p[16][4];
#pragma unroll
        for (int i = 0; i < 16; i++)
#pragma unroll
            for (int q = 0; q < 4; q++) p[i][q] = 0.f;

#pragma unroll
        for (int nt = 0; nt < 8; nt++) {
#pragma unroll
            for (int ks = 0; ks < 4; ks++) {
                uint32_t off = sw128((uint32_t)(nt * 16 + b_nr) * 128 + ks * 32 + b_ks);
                uint32_t khi[4], klo[4];
                ldsm4(khi, kb + off);
                ldsm4(klo, kb + 16384 + off);
#pragma unroll
                for (int nf = 0; nf < 2; nf++) {
                    float* cc = p[nt * 2 + nf];
                    mma16816(cc, aQ0[ks], khi + 2 * nf);
                    mma16816(cc, aQ0[ks], klo + 2 * nf);
                    mma16816(cc, aQ1[ks], khi + 2 * nf);
                }
            }
        }

        float cm0 = -1e30f, cm1 = -1e30f;
#pragma unroll
        for (int i = 0; i < 16; i++) {
            cm0 = fmaxf(cm0, fmaxf(p[i][0], p[i][1]));
            cm1 = fmaxf(cm1, fmaxf(p[i][2], p[i][3]));
        }
        cm0 = fmaxf(cm0, __shfl_xor_sync(0xffffffffu, cm0, 1));
        cm0 = fmaxf(cm0, __shfl_xor_sync(0xffffffffu, cm0, 2));
        cm1 = fmaxf(cm1, __shfl_xor_sync(0xffffffffu, cm1, 1));
        cm1 = fmaxf(cm1, __shfl_xor_sync(0xffffffffu, cm1, 2));
        float mn0 = fmaxf(m0, cm0 * SCALE_LOG2E);
        float mn1 = fmaxf(m1, cm1 * SCALE_LOG2E);
        float al0 = ex2(m0 - mn0), al1 = ex2(m1 - mn1);
        m0 = mn0; m1 = mn1;

        float sum0 = 0.f, sum1 = 0.f;
#pragma unroll
        for (int i = 0; i < 16; i++) {
            p[i][0] = ex2(p[i][0] * SCALE_LOG2E - m0); sum0 += p[i][0];
            p[i][1] = ex2(p[i][1] * SCALE_LOG2E - m0); sum0 += p[i][1];
            p[i][2] = ex2(p[i][2] * SCALE_LOG2E - m1); sum1 += p[i][2];
            p[i][3] = ex2(p[i][3] * SCALE_LOG2E - m1); sum1 += p[i][3];
        }
        sum0 += __shfl_xor_sync(0xffffffffu, sum0, 1);
        sum0 += __shfl_xor_sync(0xffffffffu, sum0, 2);
        sum1 += __shfl_xor_sync(0xffffffffu, sum1, 1);
        sum1 += __shfl_xor_sync(0xffffffffu, sum1, 2);
        l0 = al0 * l0 + sum0;
        l1 = al1 * l1 + sum1;

#pragma unroll
        for (int i = 0; i < 8; i++) {
            acc_o[i][0] *= al0; acc_o[i][1] *= al0;
            acc_o[i][2] *= al1; acc_o[i][3] *= al1;
        }

        uint32_t vb = kb + 32768;
#pragma unroll
        for (int kk = 0; kk < 8; kk++) {
            uint32_t ahi[4], alo[4];
            ahi[0] = bpack_hi(p[kk*2][0],   p[kk*2][1]);
            alo[0] = bpack_lo(p[kk*2][0],   p[kk*2][1]);
            ahi[1] = bpack_hi(p[kk*2][2],   p[kk*2][3]);
            alo[1] = bpack_lo(p[kk*2][2],   p[kk*2][3]);
            ahi[2] = bpack_hi(p[kk*2+1][0], p[kk*2+1][1]);
            alo[2] = bpack_lo(p[kk*2+1][0], p[kk*2+1][1]);
            ahi[3] = bpack_hi(p[kk*2+1][2], p[kk*2+1][3]);
            alo[3] = bpack_lo(p[kk*2+1][2], p[kk*2+1][3]);
#pragma unroll
            for (int vt = 0; vt < 4; vt++) {
                uint32_t off = sw128((uint32_t)(kk * 16 + v_row) * 128 + vt * 32 + v_cs);
                uint32_t vhi[4], vlo[4];
                ldsm4t(vhi, vb + off);
                ldsm4t(vlo, vb + 16384 + off);
#pragma unroll
                for (int nf = 0; nf < 2; nf++) {
                    float* cc = acc_o[vt * 2 + nf];
                    mma16816(cc, ahi, vhi + 2 * nf);
                    mma16816(cc, ahi, vlo + 2 * nf);
                    mma16816(cc, alo, vhi + 2 * nf);
                }
            }
        }
        __syncthreads();
        if (++stage == NSTAGE) { stage = 0; phase ^= 1; }
    }

    float inv0 = 1.f / l0, inv1 = 1.f / l1;
    int bb = bh >> 4, hh = bh & 15;
    int grow = bb * SEQ + qb * 128 + wid * 16 + (lane >> 2);
#pragma unroll
    for (int f = 0; f < 8; f++) {
        int col = hh * 64 + f * 8 + (lane & 3) * 2;
        float x0 = acc_o[f][0] * inv0, y0 = acc_o[f][1] * inv0;
        float x1 = acc_o[f][2] * inv1, y1 = acc_o[f][3] * inv1;
        size_t po0 = packed_off(grow, col, DIM);
        size_t po1 = packed_off(grow + 8, col, DIM);
        *reinterpret_cast<uint32_t*>(O0 + po0) = bpack_hi(x0, y0);
        *reinterpret_cast<uint32_t*>(O1 + po0) = bpack_lo(x0, y0);
        *reinterpret_cast<uint32_t*>(O0 + po1) = bpack_hi(x1, y1);
        *reinterpret_cast<uint32_t*>(O1 + po1) = bpack_lo(x1, y1);
    }
}

// ------------------------- reductions -------------------------
__device__ __forceinline__ float warp_sum(float v) {
#pragma unroll
    for (int o = 16; o; o >>= 1) v += __shfl_xor_sync(0xffffffffu, v, o);
    return v;
}

// ------------------------- layernorm -> packed bf16 splits -------------------------
__global__ __launch_bounds__(256) void ln_split_kernel(
    const float* __restrict__ X, const float* __restrict__ G,
    const float* __restrict__ B, char* __restrict__ Y0, char* __restrict__ Y1)
{
    __shared__ float red[8];
    int row = blockIdx.x;
    int tid = threadIdx.x;
    int lane = tid & 31, wid = tid >> 5;

    float4 v = reinterpret_cast<const float4*>(X + (size_t)row * DIM)[tid];
    float s = v.x + v.y + v.z + v.w;
    s = warp_sum(s);
    if (lane == 0) red[wid] = s;
    __syncthreads();
    if (wid == 0) {
        float t = (lane < 8) ? red[lane] : 0.f;
        t = warp_sum(t);
        if (lane == 0) red[0] = t;
    }
    __syncthreads();
    float mu = red[0] * (1.0f / DIM);
    __syncthreads();

    float4 d;
    d.x = v.x - mu; d.y = v.y - mu; d.z = v.z - mu; d.w = v.w - mu;
    float sq = d.x*d.x + d.y*d.y + d.z*d.z + d.w*d.w;
    sq = warp_sum(sq);
    if (lane == 0) red[wid] = sq;
    __syncthreads();
    if (wid == 0) {
        float t = (lane < 8) ? red[lane] : 0.f;
        t = warp_sum(t);
        if (lane == 0) red[0] = t;
    }
    __syncthreads();
    float rs = rsqrtf(red[0] * (1.0f / DIM) + 1e-5f);

    float4 g4 = reinterpret_cast<const float4*>(G)[tid];
    float4 b4 = reinterpret_cast<const float4*>(B)[tid];
    float y[4];
    y[0] = d.x * rs * g4.x + b4.x;
    y[1] = d.y * rs * g4.y + b4.y;
    y[2] = d.z * rs * g4.z + b4.z;
    y[3] = d.w * rs * g4.w + b4.w;

    size_t po = packed_off(row, tid * 4, DIM);
    uint32_t h0 = bpack_hi(y[0], y[1]), h1 = bpack_hi(y[2], y[3]);
    uint32_t l0 = bpack_lo(y[0], y[1]), l1 = bpack_lo(y[2], y[3]);
    *reinterpret_cast<uint2*>(Y0 + po) = make_uint2(h0, h1);
    *reinterpret_cast<uint2*>(Y1 + po) = make_uint2(l0, l1);
}

// ------------------------- weight transpose + split -> packed -------------------------
__global__ __launch_bounds__(256) void wsplit_kernel(
    const float* __restrict__ W, char* __restrict__ T0, char* __restrict__ T1,
    int K, int N)
{
    __shared__ float t[32][33];
    int n0 = blockIdx.x * 32, k0 = blockIdx.y * 32;
    int c = threadIdx.x & 31, r = threadIdx.x >> 5;
#pragma unroll
    for (int rr = 0; rr < 32; rr += 8)
        t[r + rr][c] = W[(size_t)(k0 + r + rr) * N + n0 + c];
    __syncthreads();
    int tx = threadIdx.x & 7;
    int ty = threadIdx.x >> 3;
    int n = n0 + ty, k = k0 + tx * 4;
    float v0 = t[tx*4+0][ty], v1 = t[tx*4+1][ty], v2 = t[tx*4+2][ty], v3 = t[tx*4+3][ty];
    size_t po = packed_off(n, k, K);
    *reinterpret_cast<uint2*>(T0 + po) = make_uint2(bpack_hi(v0, v1), bpack_hi(v2, v3));
    *reinterpret_cast<uint2*>(T1 + po) = make_uint2(bpack_lo(v0, v1), bpack_lo(v2, v3));
}

// ------------------------- launch -------------------------
extern "C" void kernel_launch(void* const* d_in, const int* in_sizes, int n_in,
                              void* d_out, int out_size)
{
    const float* x     = (const float*)d_in[0];
    const float* ln1_g = (const float*)d_in[1];
    const float* ln1_b = (const float*)d_in[2];
    const float* w_qkv = (const float*)d_in[3];
    const float* w_o   = (const float*)d_in[4];
    const float* b_o   = (const float*)d_in[5];
    const float* ln2_g = (const float*)d_in[6];
    const float* ln2_b = (const float*)d_in[7];
    const float* w1    = (const float*)d_in[8];
    const float* b1    = (const float*)d_in[9];
    const float* w2    = (const float*)d_in[10];
    const float* b2    = (const float*)d_in[11];

    float *gx;
    char *a0, *a1, *h0, *h1, *q0, *q1, *k0, *k1, *v0, *v1;
    char *wq0, *wq1, *wo0, *wo1, *w10, *w11, *w20, *w21;
    cudaGetSymbolAddress((void**)&gx,  g_x);
    cudaGetSymbolAddress((void**)&a0,  g_a0);
    cudaGetSymbolAddress((void**)&a1,  g_a1);
    cudaGetSymbolAddress((void**)&h0,  g_h0);
    cudaGetSymbolAddress((void**)&h1,  g_h1);
    cudaGetSymbolAddress((void**)&q0,  g_q0);
    cudaGetSymbolAddress((void**)&q1,  g_q1);
    cudaGetSymbolAddress((void**)&k0,  g_k0);
    cudaGetSymbolAddress((void**)&k1,  g_k1);
    cudaGetSymbolAddress((void**)&v0,  g_v0);
    cudaGetSymbolAddress((void**)&v1,  g_v1);
    cudaGetSymbolAddress((void**)&wq0, g_wq0);
    cudaGetSymbolAddress((void**)&wq1, g_wq1);
    cudaGetSymbolAddress((void**)&wo0, g_wo0);
    cudaGetSymbolAddress((void**)&wo1, g_wo1);
    cudaGetSymbolAddress((void**)&w10, g_w10);
    cudaGetSymbolAddress((void**)&w11, g_w11);
    cudaGetSymbolAddress((void**)&w20, g_w20);
    cudaGetSymbolAddress((void**)&w21, g_w21);

    cudaFuncSetAttribute(gemm_tc, cudaFuncAttributeMaxDynamicSharedMemorySize, SM_TOTAL);
    cudaFuncSetAttribute(flash_kernel, cudaFuncAttributeMaxDynamicSharedMemorySize, FL_TOTAL);

    wsplit_kernel<<<dim3(3 * DIM / 32, DIM / 32), 256>>>(w_qkv, wq0, wq1, DIM, 3 * DIM);
    wsplit_kernel<<<dim3(DIM / 32, DIM / 32), 256>>>(w_o, wo0, wo1, DIM, DIM);
    wsplit_kernel<<<dim3(MLPD / 32, DIM / 32), 256>>>(w1, w10, w11, DIM, MLPD);
    wsplit_kernel<<<dim3(DIM / 32, MLPD / 32), 256>>>(w2, w20, w21, MLPD, DIM);

    for (int layer = 0; layer < 4; layer++) {
        const float* xin = (layer == 0) ? x : gx;

        // --- attention ---
        ln_split_kernel<<<RTOK, 256>>>(xin, ln1_g, ln1_b, a0, a1);
        gemm_tc<<<dim3(3 * DIM / 128, RTOK / 128), 256, SM_TOTAL>>>(
            a0, a1, wq0, wq1, nullptr, nullptr, nullptr, q0, q1,
            k0, k1, v0, v1, 3 * DIM, DIM, 3);
        flash_kernel<<<dim3(8, NBH), 256, FL_TOTAL>>>(
            q0, q1, k0, k1, v0, v1, a0, a1);
        gemm_tc<<<dim3(DIM / 128, RTOK / 128), 256, SM_TOTAL>>>(
            a0, a1, wo0, wo1, b_o, xin, gx, nullptr, nullptr,
            nullptr, nullptr, nullptr, nullptr, DIM, DIM, 1);

        // --- MLP ---
        ln_split_kernel<<<RTOK, 256>>>(gx, ln2_g, ln2_b, a0, a1);
        gemm_tc<<<dim3(MLPD / 128, RTOK / 128), 256, SM_TOTAL>>>(
            a0, a1, w10, w11, b1, nullptr, nullptr, h0, h1,
            nullptr, nullptr, nullptr, nullptr, MLPD, DIM, 2);
        float* outp = (layer == 3) ? (float*)d_out : gx;
        gemm_tc<<<dim3(DIM / 128, RTOK / 128), 256, SM_TOTAL>>>(
            h0, h1, w20, w21, b2, gx, outp, nullptr, nullptr,
            nullptr, nullptr, nullptr, nullptr, DIM, MLPD, 1);
    }
}